// round 1
// baseline (speedup 1.0000x reference)
#include <cuda_runtime.h>

// Problem shape (fixed by the dataset)
#define T_TOK 4096   // B*S = 2*2048
#define DDIM  1024
#define FDIM  4096
#define EEXP  4
#define RRANK 4

// Scratch (static __device__ — no dynamic allocation allowed)
__device__ float g_hcomb[(size_t)T_TOK * FDIM];   // 64 MB
__device__ float g_w[T_TOK * EEXP];               // combine weights (0 for non-top2)
__device__ float g_low[T_TOK * EEXP * RRANK];     // lora_low = x @ A^T

// ---------------------------------------------------------------------------
// Kernel 1: router (softmax gate + top-2) and lora_low. One warp per token.
// ---------------------------------------------------------------------------
__global__ __launch_bounds__(256)
void router_kernel(const float* __restrict__ x, const float* __restrict__ Wg,
                   const float* __restrict__ bg, const float* __restrict__ A)
{
    int warp = threadIdx.x >> 5;
    int lane = threadIdx.x & 31;
    int t = blockIdx.x * 8 + warp;
    if (t >= T_TOK) return;

    float accg[4] = {0.f, 0.f, 0.f, 0.f};
    float acca[16] = {0.f};
    const float* xt = x + (size_t)t * DDIM;

    for (int d = lane; d < DDIM; d += 32) {
        float xv = xt[d];
#pragma unroll
        for (int e = 0; e < 4; e++) accg[e] = fmaf(xv, Wg[e * DDIM + d], accg[e]);
#pragma unroll
        for (int i = 0; i < 16; i++) acca[i] = fmaf(xv, A[i * DDIM + d], acca[i]);
    }
#pragma unroll
    for (int s = 16; s > 0; s >>= 1) {
#pragma unroll
        for (int e = 0; e < 4; e++) accg[e] += __shfl_xor_sync(0xffffffffu, accg[e], s);
#pragma unroll
        for (int i = 0; i < 16; i++) acca[i] += __shfl_xor_sync(0xffffffffu, acca[i], s);
    }

    if (lane == 0) {
        float l[4];
#pragma unroll
        for (int e = 0; e < 4; e++) l[e] = accg[e] + bg[e];
        float m = fmaxf(fmaxf(l[0], l[1]), fmaxf(l[2], l[3]));
        float p[4], s = 0.f;
#pragma unroll
        for (int e = 0; e < 4; e++) { p[e] = expf(l[e] - m); s += p[e]; }
        float inv = 1.f / s;
#pragma unroll
        for (int e = 0; e < 4; e++) p[e] *= inv;

        // top-2 (first occurrence on ties, matching jax.lax.top_k)
        int i1 = 0; float b1 = p[0];
#pragma unroll
        for (int e = 1; e < 4; e++) if (p[e] > b1) { b1 = p[e]; i1 = e; }
        int i2 = -1; float b2 = -1.f;
#pragma unroll
        for (int e = 0; e < 4; e++) if (e != i1 && p[e] > b2) { b2 = p[e]; i2 = e; }

#pragma unroll
        for (int e = 0; e < 4; e++)
            g_w[t * 4 + e] = (e == i1 || e == i2) ? p[e] : 0.f;
#pragma unroll
        for (int i = 0; i < 16; i++)
            g_low[t * 16 + i] = acca[i];
    }
}

// ---------------------------------------------------------------------------
// Tiled TN SGEMM: C[M,N] = Arow[M,K] * Brow[N,K]^T
// BM=BN=128, BK=16, 256 threads, 8x8 microtile per thread.
// MODE 0: A=x, B=Wi, fused MoE epilogue, writes g_hcomb.
// MODE 1: A=g_hcomb, B=Wo, plain store to C (the output).
// ---------------------------------------------------------------------------
template <int MODE>
__global__ __launch_bounds__(256)
void sgemm_tn(const float* __restrict__ Ain, const float* __restrict__ Bin,
              float* __restrict__ Cout, int M, int N, int K,
              const float* __restrict__ pBm)
{
    constexpr int BM = 128, BN = 128, BK = 16;
    __shared__ __align__(16) float As[BK][BM + 4];
    __shared__ __align__(16) float Bs[BK][BN + 4];

    const int tid = threadIdx.x;
    const int m0 = blockIdx.y * BM;
    const int n0 = blockIdx.x * BN;
    const int tx = tid & 15;   // n direction
    const int ty = tid >> 4;   // m direction

    const float* Aptr = (MODE == 1 ? (const float*)g_hcomb : Ain) + (size_t)m0 * K;
    const float* Bptr = Bin + (size_t)n0 * K;

    float acc[8][8];
#pragma unroll
    for (int i = 0; i < 8; i++)
#pragma unroll
        for (int j = 0; j < 8; j++) acc[i][j] = 0.f;

    for (int k0 = 0; k0 < K; k0 += BK) {
#pragma unroll
        for (int i = 0; i < 2; i++) {
            int lin = tid + i * 256;       // 0..511
            int row = lin >> 2;            // 0..127
            int c4  = lin & 3;             // which float4 in the 16-wide k slab
            float4 va = *(const float4*)(Aptr + (size_t)row * K + k0 + c4 * 4);
            As[c4 * 4 + 0][row] = va.x;
            As[c4 * 4 + 1][row] = va.y;
            As[c4 * 4 + 2][row] = va.z;
            As[c4 * 4 + 3][row] = va.w;
            float4 vb = *(const float4*)(Bptr + (size_t)row * K + k0 + c4 * 4);
            Bs[c4 * 4 + 0][row] = vb.x;
            Bs[c4 * 4 + 1][row] = vb.y;
            Bs[c4 * 4 + 2][row] = vb.z;
            Bs[c4 * 4 + 3][row] = vb.w;
        }
        __syncthreads();

#pragma unroll
        for (int kk = 0; kk < BK; kk++) {
            float a[8], b[8];
            *(float4*)&a[0] = *(const float4*)&As[kk][ty * 4];
            *(float4*)&a[4] = *(const float4*)&As[kk][64 + ty * 4];
            *(float4*)&b[0] = *(const float4*)&Bs[kk][tx * 4];
            *(float4*)&b[4] = *(const float4*)&Bs[kk][64 + tx * 4];
#pragma unroll
            for (int i = 0; i < 8; i++)
#pragma unroll
                for (int j = 0; j < 8; j++)
                    acc[i][j] = fmaf(a[i], b[j], acc[i][j]);
        }
        __syncthreads();
    }

    if (MODE == 0) {
        // Fused MoE epilogue: hcomb = sum_e w_e * relu(base + low_e . Bm_e)
        __shared__ float w_s[BM][4];
        __shared__ float low_s[BM][16];
        __shared__ float bm_s[4][BN][4];
        for (int i = tid; i < BM * 4; i += 256)
            w_s[i >> 2][i & 3] = g_w[(size_t)(m0 + (i >> 2)) * 4 + (i & 3)];
        for (int i = tid; i < BM * 16; i += 256)
            low_s[i >> 4][i & 15] = g_low[(size_t)(m0 + (i >> 4)) * 16 + (i & 15)];
        for (int i = tid; i < 4 * BN * 4; i += 256) {
            int e = i >> 9;              // 512 entries per expert (128 f * 4 r)
            int f = (i >> 2) & 127;
            int r = i & 3;
            bm_s[e][f][r] = pBm[(size_t)e * (FDIM * RRANK) + (size_t)(n0 + f) * RRANK + r];
        }
        __syncthreads();

#pragma unroll
        for (int i = 0; i < 8; i++) {
            int ml = (i < 4) ? (ty * 4 + i) : (64 + ty * 4 + (i - 4));
#pragma unroll
            for (int j = 0; j < 8; j++) {
                int nl = (j < 4) ? (tx * 4 + j) : (64 + tx * 4 + (j - 4));
                float v = acc[i][j];
                float h = 0.f;
#pragma unroll
                for (int e = 0; e < 4; e++) {
                    float lo = low_s[ml][e * 4 + 0] * bm_s[e][nl][0]
                             + low_s[ml][e * 4 + 1] * bm_s[e][nl][1]
                             + low_s[ml][e * 4 + 2] * bm_s[e][nl][2]
                             + low_s[ml][e * 4 + 3] * bm_s[e][nl][3];
                    float z = v + lo;
                    h = fmaf(w_s[ml][e], fmaxf(z, 0.f), h);
                }
                g_hcomb[(size_t)(m0 + ml) * N + n0 + nl] = h;
            }
        }
    } else {
        // Plain float4 stores to output
#pragma unroll
        for (int i = 0; i < 8; i++) {
            int ml = (i < 4) ? (ty * 4 + i) : (64 + ty * 4 + (i - 4));
            float4 v0 = make_float4(acc[i][0], acc[i][1], acc[i][2], acc[i][3]);
            float4 v1 = make_float4(acc[i][4], acc[i][5], acc[i][6], acc[i][7]);
            *(float4*)(Cout + (size_t)(m0 + ml) * N + n0 + tx * 4) = v0;
            *(float4*)(Cout + (size_t)(m0 + ml) * N + n0 + 64 + tx * 4) = v1;
        }
    }
}

// ---------------------------------------------------------------------------
extern "C" void kernel_launch(void* const* d_in, const int* in_sizes, int n_in,
                              void* d_out, int out_size)
{
    const float* x  = (const float*)d_in[0];  // [2,2048,1024]
    const float* Wg = (const float*)d_in[1];  // [4,1024]
    const float* bg = (const float*)d_in[2];  // [4]
    const float* Wi = (const float*)d_in[3];  // [4096,1024]
    const float* Wo = (const float*)d_in[4];  // [1024,4096]
    const float* A  = (const float*)d_in[5];  // [4,4,1024]
    const float* Bm = (const float*)d_in[6];  // [4,4096,4]
    float* out = (float*)d_out;               // [2,2048,1024] fp32

    // 1) router + lora_low
    router_kernel<<<T_TOK / 8, 256>>>(x, Wg, bg, A);

    // 2) base GEMM (x @ Wi^T) + fused lora/relu/top2-combine -> g_hcomb [T,F]
    {
        dim3 grid(FDIM / 128, T_TOK / 128);
        sgemm_tn<0><<<grid, 256>>>(x, Wi, nullptr, T_TOK, FDIM, DDIM, Bm);
    }

    // 3) out = g_hcomb @ Wo^T  [T,D]
    {
        dim3 grid(DDIM / 128, T_TOK / 128);
        sgemm_tn<1><<<grid, 256>>>(nullptr, Wo, out, T_TOK, DDIM, FDIM, nullptr);
    }
}

// round 7
// speedup vs baseline: 2.4122x; 2.4122x over previous
#include <cuda_runtime.h>
#include <cstdint>

// Problem shape (fixed by dataset)
#define T_TOK 4096   // B*S
#define DDIM  1024
#define FDIM  4096

// GEMM tiling
#define BM 128
#define BN 128
#define BK 32
#define LDS_PAD 36                      // row stride in 32-bit words (32 + 4)
#define TILE_WORDS (128 * LDS_PAD)      // 4608 words per operand tile

// Scratch (static __device__ — no dynamic allocation allowed)
__device__ float g_hcomb[(size_t)T_TOK * FDIM];   // 64 MB
__device__ float g_w[T_TOK * 4];
__device__ float g_low[T_TOK * 16];

__device__ __forceinline__ uint32_t f2tf32(float f) {   // unbiased RN to tf32
    uint32_t r; asm("cvt.rna.tf32.f32 %0, %1;" : "=r"(r) : "f"(f)); return r;
}
__device__ __forceinline__ void mma_tf32(float* c, const uint32_t* a, const uint32_t* b) {
    asm volatile("mma.sync.aligned.m16n8k8.row.col.f32.tf32.tf32.f32 "
                 "{%0,%1,%2,%3}, {%4,%5,%6,%7}, {%8,%9}, {%0,%1,%2,%3};"
                 : "+f"(c[0]), "+f"(c[1]), "+f"(c[2]), "+f"(c[3])
                 : "r"(a[0]), "r"(a[1]), "r"(a[2]), "r"(a[3]), "r"(b[0]), "r"(b[1]));
}

// ---------------------------------------------------------------------------
// Router as a tiny tiled GEMM: P[128tok][20] = x_tile @ [Wg;A]^T, then
// per-token softmax + top-2. 32 blocks of 256 threads, 128 tokens each.
// ---------------------------------------------------------------------------
__global__ __launch_bounds__(256)
void router_kernel(const float* __restrict__ x, const float* __restrict__ Wg,
                   const float* __restrict__ bg, const float* __restrict__ A)
{
    __shared__ float xs[128 * 36];
    __shared__ float ws[20 * 32];
    __shared__ float ps[128 * 20];

    const int tid = threadIdx.x;
    const int t0 = blockIdx.x * 128;
    const int mtok = tid & 127;
    const int jbase = (tid >> 7) * 10;
    const int rowb = tid >> 3;      // 0..31
    const int c4 = tid & 7;

    float acc[10];
#pragma unroll
    for (int j = 0; j < 10; j++) acc[j] = 0.f;

    for (int kc = 0; kc < DDIM / 32; kc++) {
        int k0 = kc * 32;
#pragma unroll
        for (int r = 0; r < 4; r++) {
            int row = rowb + 32 * r;
            float4 v = *(const float4*)(x + (size_t)(t0 + row) * DDIM + k0 + c4 * 4);
            *(float4*)&xs[row * 36 + c4 * 4] = v;
        }
        if (tid < 160) {
            int wrow = tid >> 3;   // 0..19
            const float* src = (wrow < 4) ? (Wg + (size_t)wrow * DDIM)
                                          : (A + (size_t)(wrow - 4) * DDIM);
            float4 v = *(const float4*)(src + k0 + c4 * 4);
            *(float4*)&ws[wrow * 32 + c4 * 4] = v;
        }
        __syncthreads();
#pragma unroll 8
        for (int k = 0; k < 32; k++) {
            float xv = xs[mtok * 36 + k];
#pragma unroll
            for (int j = 0; j < 10; j++)
                acc[j] = fmaf(xv, ws[(jbase + j) * 32 + k], acc[j]);
        }
        __syncthreads();
    }
#pragma unroll
    for (int j = 0; j < 10; j++) ps[mtok * 20 + jbase + j] = acc[j];
    __syncthreads();

    if (tid < 128) {
        int t = t0 + tid;
        float l[4];
#pragma unroll
        for (int e = 0; e < 4; e++) l[e] = ps[tid * 20 + e] + bg[e];
        float m = fmaxf(fmaxf(l[0], l[1]), fmaxf(l[2], l[3]));
        float p[4], s = 0.f;
#pragma unroll
        for (int e = 0; e < 4; e++) { p[e] = expf(l[e] - m); s += p[e]; }
        float inv = 1.f / s;
#pragma unroll
        for (int e = 0; e < 4; e++) p[e] *= inv;
        int i1 = 0; float b1 = p[0];
#pragma unroll
        for (int e = 1; e < 4; e++) if (p[e] > b1) { b1 = p[e]; i1 = e; }
        int i2 = -1; float b2 = -1.f;
#pragma unroll
        for (int e = 0; e < 4; e++) if (e != i1 && p[e] > b2) { b2 = p[e]; i2 = e; }
#pragma unroll
        for (int e = 0; e < 4; e++)
            g_w[t * 4 + e] = (e == i1 || e == i2) ? p[e] : 0.f;
#pragma unroll
        for (int i = 0; i < 16; i++)
            g_low[t * 16 + i] = ps[tid * 20 + 4 + i];
    }
}

// ---------------------------------------------------------------------------
// TF32 mma.sync TN GEMM: C[M,N] = A[M,K] * B[N,K]^T (both K-contiguous).
// 8 warps: warp grid 4(m) x 2(n); warp tile 32x64 = 2 x 8 m16n8k8 tiles.
// Single smem buffer + register prefetch (2 syncs/iter); static smem 36.9 KB.
// MODE 0: A=x, B=Wi, fused MoE epilogue -> g_hcomb.  MODE 1: A=g_hcomb, B=Wo.
// ---------------------------------------------------------------------------
template <int MODE>
__global__ __launch_bounds__(256)
void gemm_tc(const float* __restrict__ Ain, const float* __restrict__ Bin,
             float* __restrict__ Cout, int K, const float* __restrict__ pBm)
{
    __shared__ uint32_t smem[2 * TILE_WORDS];    // A tile | B tile
    const int tid = threadIdx.x;
    const int wid = tid >> 5, lane = tid & 31;
    const int g = lane >> 2, q = lane & 3;
    const int wm = wid & 3, wn = wid >> 2;
    const int m0 = blockIdx.y * BM;
    const int n0 = blockIdx.x * BN;
    const int rowb = tid >> 3;      // 0..31
    const int c4 = tid & 7;

    const float* Aptr = (MODE == 1 ? (const float*)g_hcomb : Ain) + (size_t)m0 * K;
    const float* Bptr = Bin + (size_t)n0 * K;

    float acc[2][8][4];
#pragma unroll
    for (int mt = 0; mt < 2; mt++)
#pragma unroll
        for (int nt = 0; nt < 8; nt++)
#pragma unroll
            for (int e = 0; e < 4; e++) acc[mt][nt][e] = 0.f;

    const int nIter = K / BK;

    // preload tile 0 and stage into smem
    float4 pa[4], pb[4];
#pragma unroll
    for (int r = 0; r < 4; r++) {
        int row = rowb + 32 * r;
        pa[r] = *(const float4*)(Aptr + (size_t)row * K + c4 * 4);
        pb[r] = *(const float4*)(Bptr + (size_t)row * K + c4 * 4);
    }
#pragma unroll
    for (int r = 0; r < 4; r++) {
        int row = rowb + 32 * r;
        uint32_t* da = &smem[row * LDS_PAD + c4 * 4];
        uint32_t* db = &smem[TILE_WORDS + row * LDS_PAD + c4 * 4];
        da[0] = f2tf32(pa[r].x); da[1] = f2tf32(pa[r].y);
        da[2] = f2tf32(pa[r].z); da[3] = f2tf32(pa[r].w);
        db[0] = f2tf32(pb[r].x); db[1] = f2tf32(pb[r].y);
        db[2] = f2tf32(pb[r].z); db[3] = f2tf32(pb[r].w);
    }
    __syncthreads();

    for (int i = 0; i < nIter; i++) {
        // prefetch next tile into registers (overlaps the MMA section)
        if (i + 1 < nIter) {
            int k0 = (i + 1) * BK;
#pragma unroll
            for (int r = 0; r < 4; r++) {
                int row = rowb + 32 * r;
                pa[r] = *(const float4*)(Aptr + (size_t)row * K + k0 + c4 * 4);
                pb[r] = *(const float4*)(Bptr + (size_t)row * K + k0 + c4 * 4);
            }
        }

        // MMA over the (single) smem buffer
#pragma unroll
        for (int kk = 0; kk < 4; kk++) {
            uint32_t a[2][4];
#pragma unroll
            for (int mt = 0; mt < 2; mt++) {
                int mrow = wm * 32 + mt * 16 + g;
                a[mt][0] = smem[mrow * LDS_PAD + kk * 8 + q];
                a[mt][1] = smem[(mrow + 8) * LDS_PAD + kk * 8 + q];
                a[mt][2] = smem[mrow * LDS_PAD + kk * 8 + q + 4];
                a[mt][3] = smem[(mrow + 8) * LDS_PAD + kk * 8 + q + 4];
            }
#pragma unroll
            for (int nt = 0; nt < 8; nt++) {
                int nrow = wn * 64 + nt * 8 + g;
                uint32_t b[2];
                b[0] = smem[TILE_WORDS + nrow * LDS_PAD + kk * 8 + q];
                b[1] = smem[TILE_WORDS + nrow * LDS_PAD + kk * 8 + q + 4];
#pragma unroll
                for (int mt = 0; mt < 2; mt++)
                    mma_tf32(acc[mt][nt], a[mt], b);
            }
        }
        __syncthreads();           // everyone done reading tile i

        if (i + 1 < nIter) {
#pragma unroll
            for (int r = 0; r < 4; r++) {
                int row = rowb + 32 * r;
                uint32_t* da = &smem[row * LDS_PAD + c4 * 4];
                uint32_t* db = &smem[TILE_WORDS + row * LDS_PAD + c4 * 4];
                da[0] = f2tf32(pa[r].x); da[1] = f2tf32(pa[r].y);
                da[2] = f2tf32(pa[r].z); da[3] = f2tf32(pa[r].w);
                db[0] = f2tf32(pb[r].x); db[1] = f2tf32(pb[r].y);
                db[2] = f2tf32(pb[r].z); db[3] = f2tf32(pb[r].w);
            }
            __syncthreads();       // tile i+1 visible
        }
    }

    if (MODE == 0) {
        // Fused MoE epilogue: hcomb = sum_e w_e * relu(base + low_e . Bm_e)
        float* w_s   = (float*)&smem[0];       // [128][4]
        float* low_s = (float*)&smem[512];     // [128][16]
        float* bm_s  = (float*)&smem[2560];    // [4][128][4]
        for (int i = tid; i < 128 * 4; i += 256)
            w_s[i] = g_w[(size_t)(m0 + (i >> 2)) * 4 + (i & 3)];
        for (int i = tid; i < 128 * 16; i += 256)
            low_s[i] = g_low[(size_t)(m0 + (i >> 4)) * 16 + (i & 15)];
        for (int i = tid; i < 4 * 128 * 4; i += 256) {
            int e = i >> 9, f = (i >> 2) & 127, r = i & 3;
            bm_s[i] = pBm[(size_t)e * (FDIM * 4) + (size_t)(n0 + f) * 4 + r];
        }
        __syncthreads();

#pragma unroll
        for (int mt = 0; mt < 2; mt++) {
#pragma unroll
            for (int half = 0; half < 2; half++) {
                int r = wm * 32 + mt * 16 + g + half * 8;     // local row
                float4 wv = *(const float4*)&w_s[r * 4];
                float4 lv[4];
#pragma unroll
                for (int e = 0; e < 4; e++) lv[e] = *(const float4*)&low_s[r * 16 + e * 4];
                float* dst = g_hcomb + (size_t)(m0 + r) * FDIM + n0;
#pragma unroll
                for (int nt = 0; nt < 8; nt++) {
                    int cl = wn * 64 + nt * 8 + 2 * q;
                    float o[2];
#pragma unroll
                    for (int j = 0; j < 2; j++) {
                        float base = acc[mt][nt][half * 2 + j];
                        int col = cl + j;
                        float h = 0.f;
#pragma unroll
                        for (int e = 0; e < 4; e++) {
                            float4 bm = *(const float4*)&bm_s[(e * 128 + col) * 4];
                            float lo = lv[e].x * bm.x + lv[e].y * bm.y
                                     + lv[e].z * bm.z + lv[e].w * bm.w;
                            float wcomp = (e == 0) ? wv.x : (e == 1) ? wv.y
                                        : (e == 2) ? wv.z : wv.w;
                            h = fmaf(wcomp, fmaxf(base + lo, 0.f), h);
                        }
                        o[j] = h;
                    }
                    *(float2*)(dst + cl) = make_float2(o[0], o[1]);
                }
            }
        }
    } else {
#pragma unroll
        for (int mt = 0; mt < 2; mt++) {
#pragma unroll
            for (int half = 0; half < 2; half++) {
                int r = wm * 32 + mt * 16 + g + half * 8;
                float* dst = Cout + (size_t)(m0 + r) * DDIM + n0;
#pragma unroll
                for (int nt = 0; nt < 8; nt++) {
                    int cl = wn * 64 + nt * 8 + 2 * q;
                    *(float2*)(dst + cl) =
                        make_float2(acc[mt][nt][half * 2], acc[mt][nt][half * 2 + 1]);
                }
            }
        }
    }
}

// ---------------------------------------------------------------------------
extern "C" void kernel_launch(void* const* d_in, const int* in_sizes, int n_in,
                              void* d_out, int out_size)
{
    const float* x  = (const float*)d_in[0];
    const float* Wg = (const float*)d_in[1];
    const float* bg = (const float*)d_in[2];
    const float* Wi = (const float*)d_in[3];
    const float* Wo = (const float*)d_in[4];
    const float* A  = (const float*)d_in[5];
    const float* Bm = (const float*)d_in[6];
    float* out = (float*)d_out;

    router_kernel<<<T_TOK / 128, 256>>>(x, Wg, bg, A);

    gemm_tc<0><<<dim3(FDIM / BN, T_TOK / BM), 256>>>(x, Wi, nullptr, DDIM, Bm);
    gemm_tc<1><<<dim3(DDIM / BN, T_TOK / BM), 256>>>(nullptr, Wo, out, FDIM, nullptr);
}

// round 10
// speedup vs baseline: 2.8058x; 1.1632x over previous
#include <cuda_runtime.h>
#include <cstdint>

// Problem shape (fixed by dataset)
#define T_TOK 4096   // B*S
#define DDIM  1024
#define FDIM  4096

// GEMM tiling
#define BM 128
#define BN 128
#define BK 32
#define LDS_PAD 36                       // words per smem row (32 + 4)
#define TILE_WORDS (128 * LDS_PAD)       // 4608 words per operand tile
#define STAGE_WORDS (2 * TILE_WORDS)     // A + B per stage
#define NSTAGE 3
#define SMEM_BYTES_G (NSTAGE * STAGE_WORDS * 4)   // 110592

// Scratch (static __device__ — no dynamic allocation allowed)
__device__ uint32_t g_xt[(size_t)T_TOK * DDIM];    // x as tf32 bits, 16 MB
__device__ uint32_t g_wit[(size_t)FDIM * DDIM];    // Wi as tf32 bits, 16 MB
__device__ uint32_t g_wot[(size_t)DDIM * FDIM];    // Wo as tf32 bits, 16 MB
__device__ uint32_t g_hcomb[(size_t)T_TOK * FDIM]; // hcomb as tf32 bits, 64 MB
__device__ float g_w[T_TOK * 4];
__device__ float g_low[T_TOK * 16];

__device__ __forceinline__ uint32_t f2tf32(float f) {   // unbiased RN to tf32
    uint32_t r; asm("cvt.rna.tf32.f32 %0, %1;" : "=r"(r) : "f"(f)); return r;
}
__device__ __forceinline__ uint32_t smem_u32(const void* p) {
    uint32_t a;
    asm("{ .reg .u64 t; cvta.to.shared.u64 t, %1; cvt.u32.u64 %0, t; }" : "=r"(a) : "l"(p));
    return a;
}
__device__ __forceinline__ void mma_tf32(float* c, const uint32_t* a, const uint32_t* b) {
    asm volatile("mma.sync.aligned.m16n8k8.row.col.f32.tf32.tf32.f32 "
                 "{%0,%1,%2,%3}, {%4,%5,%6,%7}, {%8,%9}, {%0,%1,%2,%3};"
                 : "+f"(c[0]), "+f"(c[1]), "+f"(c[2]), "+f"(c[3])
                 : "r"(a[0]), "r"(a[1]), "r"(a[2]), "r"(a[3]), "r"(b[0]), "r"(b[1]));
}

// ---------------------------------------------------------------------------
// Elementwise fp32 -> tf32(bits) conversion, vectorized, grid-stride.
// ---------------------------------------------------------------------------
__global__ __launch_bounds__(256)
void conv_tf32(const float4* __restrict__ src, uint4* __restrict__ dst, int n4)
{
    int i = blockIdx.x * blockDim.x + threadIdx.x;
    int stride = gridDim.x * blockDim.x;
    for (; i < n4; i += stride) {
        float4 v = src[i];
        dst[i] = make_uint4(f2tf32(v.x), f2tf32(v.y), f2tf32(v.z), f2tf32(v.w));
    }
}

// ---------------------------------------------------------------------------
// Router: 128 blocks x 640 threads; 32 tokens/block; thread = (token, output j).
// Outputs j: 0..3 = gate logits, 4..19 = lora_low. Then softmax + top-2.
// ---------------------------------------------------------------------------
#define RT_TB 32
__global__ __launch_bounds__(640)
void router_kernel(const float* __restrict__ x, const float* __restrict__ Wg,
                   const float* __restrict__ bg, const float* __restrict__ A)
{
    __shared__ float xs[RT_TB * 36];
    __shared__ float ws[20 * 37];
    __shared__ float ps[RT_TB * 20];

    const int tid = threadIdx.x;            // 0..639
    const int t0 = blockIdx.x * RT_TB;
    const int tok = tid / 20;
    const int j = tid % 20;
    const int wr = tid >> 5, wc = tid & 31;  // 20 weight rows x 32 cols

    float acc = 0.f;
    for (int kc = 0; kc < DDIM / 32; kc++) {
        int k0 = kc * 32;
        if (tid < 256) {
            int row = tid >> 3, c4 = tid & 7;
            float4 v = *(const float4*)(x + (size_t)(t0 + row) * DDIM + k0 + c4 * 4);
            *(float4*)&xs[row * 36 + c4 * 4] = v;
        }
        {
            const float* src = (wr < 4) ? (Wg + (size_t)wr * DDIM)
                                        : (A + (size_t)(wr - 4) * DDIM);
            ws[wr * 37 + wc] = src[k0 + wc];
        }
        __syncthreads();
#pragma unroll 8
        for (int k = 0; k < 32; k++)
            acc = fmaf(xs[tok * 36 + k], ws[j * 37 + k], acc);
        __syncthreads();
    }
    ps[tok * 20 + j] = acc;
    __syncthreads();

    if (tid < RT_TB) {
        int t = t0 + tid;
        float l[4];
#pragma unroll
        for (int e = 0; e < 4; e++) l[e] = ps[tid * 20 + e] + bg[e];
        float m = fmaxf(fmaxf(l[0], l[1]), fmaxf(l[2], l[3]));
        float p[4], s = 0.f;
#pragma unroll
        for (int e = 0; e < 4; e++) { p[e] = expf(l[e] - m); s += p[e]; }
        float inv = 1.f / s;
#pragma unroll
        for (int e = 0; e < 4; e++) p[e] *= inv;
        int i1 = 0; float b1 = p[0];
#pragma unroll
        for (int e = 1; e < 4; e++) if (p[e] > b1) { b1 = p[e]; i1 = e; }
        int i2 = -1; float b2 = -1.f;
#pragma unroll
        for (int e = 0; e < 4; e++) if (e != i1 && p[e] > b2) { b2 = p[e]; i2 = e; }
#pragma unroll
        for (int e = 0; e < 4; e++)
            g_w[t * 4 + e] = (e == i1 || e == i2) ? p[e] : 0.f;
#pragma unroll
        for (int i = 0; i < 16; i++)
            g_low[t * 16 + i] = ps[tid * 20 + 4 + i];
    }
}

// ---------------------------------------------------------------------------
// TF32 mma.sync TN GEMM with 3-stage cp.async pipeline, 1 sync/iter.
// Operands are pre-converted tf32 bits in gmem. 8 warps, warp tile 32x64.
// MODE 0: A=g_xt, B=g_wit, fused MoE epilogue -> g_hcomb (tf32-rounded bits).
// MODE 1: A=g_hcomb, B=g_wot -> Cout (fp32).
// ---------------------------------------------------------------------------
__device__ __forceinline__ void issue_tile(uint32_t sbaseA, const uint32_t* __restrict__ Ag,
                                           uint32_t sbaseB, const uint32_t* __restrict__ Bg,
                                           int K, int k0, int tid)
{
#pragma unroll
    for (int t = 0; t < 4; t++) {           // 4*256 = 1024 chunks: full 128 rows
        int idx = tid + t * 256;
        int row = idx >> 3, c4 = idx & 7;
        uint32_t off = (uint32_t)(row * LDS_PAD + c4 * 4) * 4;
        const void* ga = Ag + (size_t)row * K + k0 + c4 * 4;
        const void* gb = Bg + (size_t)row * K + k0 + c4 * 4;
        asm volatile("cp.async.cg.shared.global [%0], [%1], 16;" :: "r"(sbaseA + off), "l"(ga));
        asm volatile("cp.async.cg.shared.global [%0], [%1], 16;" :: "r"(sbaseB + off), "l"(gb));
    }
}

template <int MODE>
__global__ __launch_bounds__(256, 2)
void gemm_tc(const uint32_t* __restrict__ Ain, const uint32_t* __restrict__ Bin,
             float* __restrict__ Cout, int K, const float* __restrict__ pBm)
{
    extern __shared__ uint32_t smem[];
    const uint32_t sb = smem_u32(smem);
    const int tid = threadIdx.x;
    const int wid = tid >> 5, lane = tid & 31;
    const int g = lane >> 2, q = lane & 3;
    const int wm = wid & 3, wn = wid >> 2;
    const int m0 = blockIdx.y * BM;
    const int n0 = blockIdx.x * BN;

    const uint32_t* Aptr = Ain + (size_t)m0 * K;
    const uint32_t* Bptr = Bin + (size_t)n0 * K;

    float acc[2][8][4];
#pragma unroll
    for (int mt = 0; mt < 2; mt++)
#pragma unroll
        for (int nt = 0; nt < 8; nt++)
#pragma unroll
            for (int e = 0; e < 4; e++) acc[mt][nt][e] = 0.f;

    const int nIter = K / BK;

    // prologue: stages 0 and 1
    issue_tile(sb, Aptr, sb + TILE_WORDS * 4, Bptr, K, 0, tid);
    asm volatile("cp.async.commit_group;");
    issue_tile(sb + STAGE_WORDS * 4, Aptr, sb + (STAGE_WORDS + TILE_WORDS) * 4, Bptr, K, BK, tid);
    asm volatile("cp.async.commit_group;");

    int buf = 0;
    for (int i = 0; i < nIter; i++) {
        if (i + 2 < nIter) {
            asm volatile("cp.async.wait_group 1;");
        } else {
            asm volatile("cp.async.wait_group 0;");
        }
        __syncthreads();

        if (i + 2 < nIter) {
            int wbuf = buf + 2; if (wbuf >= NSTAGE) wbuf -= NSTAGE;
            uint32_t wb = sb + (uint32_t)(wbuf * STAGE_WORDS) * 4;
            issue_tile(wb, Aptr, wb + TILE_WORDS * 4, Bptr, K, (i + 2) * BK, tid);
            asm volatile("cp.async.commit_group;");
        }

        const uint32_t* As = smem + buf * STAGE_WORDS;
        const uint32_t* Bs = As + TILE_WORDS;
#pragma unroll
        for (int kk = 0; kk < 4; kk++) {
            uint32_t a[2][4];
#pragma unroll
            for (int mt = 0; mt < 2; mt++) {
                int mrow = wm * 32 + mt * 16 + g;
                a[mt][0] = As[mrow * LDS_PAD + kk * 8 + q];
                a[mt][1] = As[(mrow + 8) * LDS_PAD + kk * 8 + q];
                a[mt][2] = As[mrow * LDS_PAD + kk * 8 + q + 4];
                a[mt][3] = As[(mrow + 8) * LDS_PAD + kk * 8 + q + 4];
            }
#pragma unroll
            for (int nt = 0; nt < 8; nt++) {
                int nrow = wn * 64 + nt * 8 + g;
                uint32_t b[2];
                b[0] = Bs[nrow * LDS_PAD + kk * 8 + q];
                b[1] = Bs[nrow * LDS_PAD + kk * 8 + q + 4];
#pragma unroll
                for (int mt = 0; mt < 2; mt++)
                    mma_tf32(acc[mt][nt], a[mt], b);
            }
        }
        if (++buf >= NSTAGE) buf = 0;
    }
    __syncthreads();     // all MMA reads done before smem reuse by epilogue

    if (MODE == 0) {
        // Fused MoE epilogue: hcomb = sum_e w_e * relu(base + low_e . Bm_e)
        float* w_s   = (float*)&smem[0];       // [128][4]
        float* low_s = (float*)&smem[512];     // [128][16]
        float* bm_s  = (float*)&smem[2560];    // [4][128][4]
        for (int i = tid; i < 128 * 4; i += 256)
            w_s[i] = g_w[(size_t)(m0 + (i >> 2)) * 4 + (i & 3)];
        for (int i = tid; i < 128 * 16; i += 256)
            low_s[i] = g_low[(size_t)(m0 + (i >> 4)) * 16 + (i & 15)];
        for (int i = tid; i < 4 * 128 * 4; i += 256) {
            int e = i >> 9, f = (i >> 2) & 127, r = i & 3;
            bm_s[i] = pBm[(size_t)e * (FDIM * 4) + (size_t)(n0 + f) * 4 + r];
        }
        __syncthreads();

#pragma unroll
        for (int mt = 0; mt < 2; mt++) {
#pragma unroll
            for (int half = 0; half < 2; half++) {
                int r = wm * 32 + mt * 16 + g + half * 8;     // local row
                float4 wv = *(const float4*)&w_s[r * 4];
                float4 lv[4];
#pragma unroll
                for (int e = 0; e < 4; e++) lv[e] = *(const float4*)&low_s[r * 16 + e * 4];
                uint32_t* dst = g_hcomb + (size_t)(m0 + r) * FDIM + n0;
#pragma unroll
                for (int nt = 0; nt < 8; nt++) {
                    int cl = wn * 64 + nt * 8 + 2 * q;
                    uint32_t o[2];
#pragma unroll
                    for (int j = 0; j < 2; j++) {
                        float base = acc[mt][nt][half * 2 + j];
                        int col = cl + j;
                        float h = 0.f;
#pragma unroll
                        for (int e = 0; e < 4; e++) {
                            float4 bm = *(const float4*)&bm_s[(e * 128 + col) * 4];
                            float lo = lv[e].x * bm.x + lv[e].y * bm.y
                                     + lv[e].z * bm.z + lv[e].w * bm.w;
                            float wcomp = (e == 0) ? wv.x : (e == 1) ? wv.y
                                        : (e == 2) ? wv.z : wv.w;
                            h = fmaf(wcomp, fmaxf(base + lo, 0.f), h);
                        }
                        o[j] = f2tf32(h);   // pre-round for GEMM2's A operand
                    }
                    *(uint2*)(dst + cl) = make_uint2(o[0], o[1]);
                }
            }
        }
    } else {
#pragma unroll
        for (int mt = 0; mt < 2; mt++) {
#pragma unroll
            for (int half = 0; half < 2; half++) {
                int r = wm * 32 + mt * 16 + g + half * 8;
                float* dst = Cout + (size_t)(m0 + r) * DDIM + n0;
#pragma unroll
                for (int nt = 0; nt < 8; nt++) {
                    int cl = wn * 64 + nt * 8 + 2 * q;
                    *(float2*)(dst + cl) =
                        make_float2(acc[mt][nt][half * 2], acc[mt][nt][half * 2 + 1]);
                }
            }
        }
    }
}

// ---------------------------------------------------------------------------
extern "C" void kernel_launch(void* const* d_in, const int* in_sizes, int n_in,
                              void* d_out, int out_size)
{
    const float* x  = (const float*)d_in[0];
    const float* Wg = (const float*)d_in[1];
    const float* bg = (const float*)d_in[2];
    const float* Wi = (const float*)d_in[3];
    const float* Wo = (const float*)d_in[4];
    const float* A  = (const float*)d_in[5];
    const float* Bm = (const float*)d_in[6];
    float* out = (float*)d_out;

    // dynamic-smem opt-in (idempotent host-side attribute set; no stream op)
    cudaFuncSetAttribute(gemm_tc<0>, cudaFuncAttributeMaxDynamicSharedMemorySize, SMEM_BYTES_G);
    cudaFuncSetAttribute(gemm_tc<1>, cudaFuncAttributeMaxDynamicSharedMemorySize, SMEM_BYTES_G);

    uint32_t* xt = nullptr;  cudaGetSymbolAddress((void**)&xt,  g_xt);
    uint32_t* wit = nullptr; cudaGetSymbolAddress((void**)&wit, g_wit);
    uint32_t* wot = nullptr; cudaGetSymbolAddress((void**)&wot, g_wot);
    uint32_t* hc = nullptr;  cudaGetSymbolAddress((void**)&hc,  g_hcomb);

    // pre-convert operands to tf32 bits
    conv_tf32<<<1024, 256>>>((const float4*)x,  (uint4*)xt,  T_TOK * DDIM / 4);
    conv_tf32<<<1024, 256>>>((const float4*)Wi, (uint4*)wit, FDIM * DDIM / 4);
    conv_tf32<<<1024, 256>>>((const float4*)Wo, (uint4*)wot, DDIM * FDIM / 4);

    router_kernel<<<T_TOK / RT_TB, 640>>>(x, Wg, bg, A);

    gemm_tc<0><<<dim3(FDIM / BN, T_TOK / BM), 256, SMEM_BYTES_G>>>(xt, wit, nullptr, DDIM, Bm);
    gemm_tc<1><<<dim3(DDIM / BN, T_TOK / BM), 256, SMEM_BYTES_G>>>(hc, wot, out, FDIM, nullptr);
}

// round 11
// speedup vs baseline: 3.4843x; 1.2418x over previous
#include <cuda_runtime.h>
#include <cuda_fp16.h>
#include <cstdint>

// Problem shape (fixed by dataset)
#define T_TOK 4096   // B*S
#define DDIM  1024
#define FDIM  4096

// GEMM tiling (halves). BK = 64 halves = 32 words = 128 B/row.
#define BM 128
#define BN 128
#define BKW 32                           // 32-bit words of k per stage-row
#define LDS_PAD 36                       // words per smem row (32 + 4)
#define TILE_WORDS (128 * LDS_PAD)       // 4608 words per operand tile
#define STAGE_WORDS (2 * TILE_WORDS)
#define NSTAGE 3
#define SMEM_BYTES_G (NSTAGE * STAGE_WORDS * 4)   // 110592
#define SMEM_BYTES_R (20 * DDIM * 4)              // 81920 (router weights)

// Scratch (static __device__ — no dynamic allocation allowed)
__device__ uint32_t g_xh[(size_t)T_TOK * DDIM / 2];    // x as half2 words, 8 MB
__device__ uint32_t g_wih[(size_t)FDIM * DDIM / 2];    // Wi as half2 words, 8 MB
__device__ uint32_t g_woh[(size_t)DDIM * FDIM / 2];    // Wo as half2 words, 8 MB
__device__ uint32_t g_hcomb[(size_t)T_TOK * FDIM / 2]; // hcomb as half2 words, 32 MB
__device__ float g_w[T_TOK * 4];
__device__ float g_low[T_TOK * 16];

__device__ __forceinline__ uint32_t smem_u32(const void* p) {
    uint32_t a;
    asm("{ .reg .u64 t; cvta.to.shared.u64 t, %1; cvt.u32.u64 %0, t; }" : "=r"(a) : "l"(p));
    return a;
}
__device__ __forceinline__ void mma_f16(float* c, const uint32_t* a, const uint32_t* b) {
    asm volatile("mma.sync.aligned.m16n8k16.row.col.f32.f16.f16.f32 "
                 "{%0,%1,%2,%3}, {%4,%5,%6,%7}, {%8,%9}, {%0,%1,%2,%3};"
                 : "+f"(c[0]), "+f"(c[1]), "+f"(c[2]), "+f"(c[3])
                 : "r"(a[0]), "r"(a[1]), "r"(a[2]), "r"(a[3]), "r"(b[0]), "r"(b[1]));
}
__device__ __forceinline__ uint32_t pack_h2(float lo, float hi) {
    __half2 h = __floats2half2_rn(lo, hi);       // x = lo (low half), y = hi
    return *(uint32_t*)&h;
}

// ---------------------------------------------------------------------------
// fp32 -> half2 conversion, vectorized, grid-stride.
// ---------------------------------------------------------------------------
__global__ __launch_bounds__(256)
void conv_h(const float4* __restrict__ src, uint2* __restrict__ dst, int n4)
{
    int i = blockIdx.x * blockDim.x + threadIdx.x;
    int stride = gridDim.x * blockDim.x;
    for (; i < n4; i += stride) {
        float4 v = src[i];
        dst[i] = make_uint2(pack_h2(v.x, v.y), pack_h2(v.z, v.w));
    }
}

// ---------------------------------------------------------------------------
// Router: 128 blocks x 512 threads. All 20 weight rows staged in 80 KB smem.
// Each warp handles 2 tokens; 8 prefetched float4 x-loads per token (high MLP).
// ---------------------------------------------------------------------------
__global__ __launch_bounds__(512)
void router_kernel(const float* __restrict__ x, const float* __restrict__ Wg,
                   const float* __restrict__ bg, const float* __restrict__ A)
{
    extern __shared__ float4 ws4[];              // [20][256] float4 = 80 KB
    const int tid = threadIdx.x;
    const int w = tid >> 5, lane = tid & 31;
    const int t0 = blockIdx.x * 32;

    for (int i = tid; i < 20 * 256; i += 512) {
        int j = i >> 8, o = i & 255;
        const float* src = (j < 4) ? (Wg + (size_t)j * DDIM) : (A + (size_t)(j - 4) * DDIM);
        ws4[i] = ((const float4*)src)[o];
    }
    __syncthreads();

#pragma unroll
    for (int tt = 0; tt < 2; tt++) {
        int tok = t0 + w * 2 + tt;
        const float4* xt = (const float4*)(x + (size_t)tok * DDIM);
        float4 xv[8];
#pragma unroll
        for (int i = 0; i < 8; i++) xv[i] = xt[i * 32 + lane];
        float acc[20];
#pragma unroll
        for (int j = 0; j < 20; j++) acc[j] = 0.f;
#pragma unroll
        for (int i = 0; i < 8; i++) {
#pragma unroll
            for (int j = 0; j < 20; j++) {
                float4 wv = ws4[j * 256 + i * 32 + lane];
                acc[j] += xv[i].x * wv.x + xv[i].y * wv.y + xv[i].z * wv.z + xv[i].w * wv.w;
            }
        }
#pragma unroll
        for (int s = 16; s > 0; s >>= 1)
#pragma unroll
            for (int j = 0; j < 20; j++) acc[j] += __shfl_xor_sync(0xffffffffu, acc[j], s);

        if (lane == 0) {
            float l[4];
#pragma unroll
            for (int e = 0; e < 4; e++) l[e] = acc[e] + bg[e];
            float m = fmaxf(fmaxf(l[0], l[1]), fmaxf(l[2], l[3]));
            float p[4], s = 0.f;
#pragma unroll
            for (int e = 0; e < 4; e++) { p[e] = expf(l[e] - m); s += p[e]; }
            float inv = 1.f / s;
#pragma unroll
            for (int e = 0; e < 4; e++) p[e] *= inv;
            int i1 = 0; float b1 = p[0];
#pragma unroll
            for (int e = 1; e < 4; e++) if (p[e] > b1) { b1 = p[e]; i1 = e; }
            int i2 = -1; float b2 = -1.f;
#pragma unroll
            for (int e = 0; e < 4; e++) if (e != i1 && p[e] > b2) { b2 = p[e]; i2 = e; }
#pragma unroll
            for (int e = 0; e < 4; e++)
                g_w[tok * 4 + e] = (e == i1 || e == i2) ? p[e] : 0.f;
#pragma unroll
            for (int i = 0; i < 16; i++)
                g_low[tok * 16 + i] = acc[4 + i];
        }
    }
}

// ---------------------------------------------------------------------------
// FP16 mma.sync m16n8k16 TN GEMM, 3-stage cp.async pipeline, 1 sync/iter.
// Operands are half2 words in gmem (Kw = K/2 words per row). 8 warps,
// warp tile 32x64. BK = 64 halves per iter (4 k16 sub-steps).
// MODE 0: A=g_xh, B=g_wih, fused MoE epilogue -> g_hcomb (half).
// MODE 1: A=g_hcomb, B=g_woh -> Cout (fp32).
// ---------------------------------------------------------------------------
__device__ __forceinline__ void issue_tile(uint32_t sbaseA, const uint32_t* __restrict__ Ag,
                                           uint32_t sbaseB, const uint32_t* __restrict__ Bg,
                                           int Kw, int k0w, int tid)
{
#pragma unroll
    for (int t = 0; t < 4; t++) {           // 1024 chunks: 128 rows x 8 chunks
        int idx = tid + t * 256;
        int row = idx >> 3, c4 = idx & 7;
        uint32_t off = (uint32_t)(row * LDS_PAD + c4 * 4) * 4;
        const void* ga = Ag + (size_t)row * Kw + k0w + c4 * 4;
        const void* gb = Bg + (size_t)row * Kw + k0w + c4 * 4;
        asm volatile("cp.async.cg.shared.global [%0], [%1], 16;" :: "r"(sbaseA + off), "l"(ga));
        asm volatile("cp.async.cg.shared.global [%0], [%1], 16;" :: "r"(sbaseB + off), "l"(gb));
    }
}

template <int MODE>
__global__ __launch_bounds__(256, 2)
void gemm_h(const uint32_t* __restrict__ Ain, const uint32_t* __restrict__ Bin,
            float* __restrict__ Cout, int Kw, const float* __restrict__ pBm)
{
    extern __shared__ uint32_t smem[];
    const uint32_t sb = smem_u32(smem);
    const int tid = threadIdx.x;
    const int wid = tid >> 5, lane = tid & 31;
    const int g = lane >> 2, q = lane & 3;
    const int wm = wid & 3, wn = wid >> 2;
    const int m0 = blockIdx.y * BM;
    const int n0 = blockIdx.x * BN;

    const uint32_t* Aptr = Ain + (size_t)m0 * Kw;
    const uint32_t* Bptr = Bin + (size_t)n0 * Kw;

    float acc[2][8][4];
#pragma unroll
    for (int mt = 0; mt < 2; mt++)
#pragma unroll
        for (int nt = 0; nt < 8; nt++)
#pragma unroll
            for (int e = 0; e < 4; e++) acc[mt][nt][e] = 0.f;

    const int nIter = Kw / BKW;

    issue_tile(sb, Aptr, sb + TILE_WORDS * 4, Bptr, Kw, 0, tid);
    asm volatile("cp.async.commit_group;");
    issue_tile(sb + STAGE_WORDS * 4, Aptr, sb + (STAGE_WORDS + TILE_WORDS) * 4, Bptr, Kw, BKW, tid);
    asm volatile("cp.async.commit_group;");

    int buf = 0;
    for (int i = 0; i < nIter; i++) {
        if (i + 2 < nIter) {
            asm volatile("cp.async.wait_group 1;");
        } else {
            asm volatile("cp.async.wait_group 0;");
        }
        __syncthreads();

        if (i + 2 < nIter) {
            int wbuf = buf + 2; if (wbuf >= NSTAGE) wbuf -= NSTAGE;
            uint32_t wb = sb + (uint32_t)(wbuf * STAGE_WORDS) * 4;
            issue_tile(wb, Aptr, wb + TILE_WORDS * 4, Bptr, Kw, (i + 2) * BKW, tid);
            asm volatile("cp.async.commit_group;");
        }

        const uint32_t* As = smem + buf * STAGE_WORDS;
        const uint32_t* Bs = As + TILE_WORDS;
#pragma unroll
        for (int kk = 0; kk < 4; kk++) {          // each kk = 16 halves of k
            uint32_t a[2][4];
#pragma unroll
            for (int mt = 0; mt < 2; mt++) {
                int mrow = wm * 32 + mt * 16 + g;
                a[mt][0] = As[mrow * LDS_PAD + kk * 8 + q];
                a[mt][1] = As[(mrow + 8) * LDS_PAD + kk * 8 + q];
                a[mt][2] = As[mrow * LDS_PAD + kk * 8 + q + 4];
                a[mt][3] = As[(mrow + 8) * LDS_PAD + kk * 8 + q + 4];
            }
#pragma unroll
            for (int nt = 0; nt < 8; nt++) {
                int nrow = wn * 64 + nt * 8 + g;
                uint32_t b[2];
                b[0] = Bs[nrow * LDS_PAD + kk * 8 + q];
                b[1] = Bs[nrow * LDS_PAD + kk * 8 + q + 4];
#pragma unroll
                for (int mt = 0; mt < 2; mt++)
                    mma_f16(acc[mt][nt], a[mt], b);
            }
        }
        if (++buf >= NSTAGE) buf = 0;
    }
    __syncthreads();     // all MMA reads done before smem reuse by epilogue

    if (MODE == 0) {
        // Fused MoE epilogue: hcomb = sum_e w_e * relu(base + low_e . Bm_e)
        float* w_s   = (float*)&smem[0];       // [128][4]
        float* low_s = (float*)&smem[512];     // [128][16]
        float* bm_s  = (float*)&smem[2560];    // [4][128][4]
        for (int i = tid; i < 128 * 4; i += 256)
            w_s[i] = g_w[(size_t)(m0 + (i >> 2)) * 4 + (i & 3)];
        for (int i = tid; i < 128 * 16; i += 256)
            low_s[i] = g_low[(size_t)(m0 + (i >> 4)) * 16 + (i & 15)];
        for (int i = tid; i < 4 * 128 * 4; i += 256) {
            int e = i >> 9, f = (i >> 2) & 127, r = i & 3;
            bm_s[i] = pBm[(size_t)e * (FDIM * 4) + (size_t)(n0 + f) * 4 + r];
        }
        __syncthreads();

#pragma unroll
        for (int mt = 0; mt < 2; mt++) {
#pragma unroll
            for (int half = 0; half < 2; half++) {
                int r = wm * 32 + mt * 16 + g + half * 8;     // local row
                float4 wv = *(const float4*)&w_s[r * 4];
                float4 lv[4];
#pragma unroll
                for (int e = 0; e < 4; e++) lv[e] = *(const float4*)&low_s[r * 16 + e * 4];
                uint32_t* dst = g_hcomb + (size_t)(m0 + r) * (FDIM / 2) + n0 / 2;
#pragma unroll
                for (int nt = 0; nt < 8; nt++) {
                    int cl = wn * 64 + nt * 8 + 2 * q;        // even column
                    float o[2];
#pragma unroll
                    for (int j = 0; j < 2; j++) {
                        float base = acc[mt][nt][half * 2 + j];
                        int col = cl + j;
                        float h = 0.f;
#pragma unroll
                        for (int e = 0; e < 4; e++) {
                            float4 bm = *(const float4*)&bm_s[(e * 128 + col) * 4];
                            float lo = lv[e].x * bm.x + lv[e].y * bm.y
                                     + lv[e].z * bm.z + lv[e].w * bm.w;
                            float wcomp = (e == 0) ? wv.x : (e == 1) ? wv.y
                                        : (e == 2) ? wv.z : wv.w;
                            h = fmaf(wcomp, fmaxf(base + lo, 0.f), h);
                        }
                        o[j] = h;
                    }
                    dst[cl >> 1] = pack_h2(o[0], o[1]);
                }
            }
        }
    } else {
#pragma unroll
        for (int mt = 0; mt < 2; mt++) {
#pragma unroll
            for (int half = 0; half < 2; half++) {
                int r = wm * 32 + mt * 16 + g + half * 8;
                float* dst = Cout + (size_t)(m0 + r) * DDIM + n0;
#pragma unroll
                for (int nt = 0; nt < 8; nt++) {
                    int cl = wn * 64 + nt * 8 + 2 * q;
                    *(float2*)(dst + cl) =
                        make_float2(acc[mt][nt][half * 2], acc[mt][nt][half * 2 + 1]);
                }
            }
        }
    }
}

// ---------------------------------------------------------------------------
extern "C" void kernel_launch(void* const* d_in, const int* in_sizes, int n_in,
                              void* d_out, int out_size)
{
    const float* x  = (const float*)d_in[0];
    const float* Wg = (const float*)d_in[1];
    const float* bg = (const float*)d_in[2];
    const float* Wi = (const float*)d_in[3];
    const float* Wo = (const float*)d_in[4];
    const float* A  = (const float*)d_in[5];
    const float* Bm = (const float*)d_in[6];
    float* out = (float*)d_out;

    cudaFuncSetAttribute(gemm_h<0>, cudaFuncAttributeMaxDynamicSharedMemorySize, SMEM_BYTES_G);
    cudaFuncSetAttribute(gemm_h<1>, cudaFuncAttributeMaxDynamicSharedMemorySize, SMEM_BYTES_G);
    cudaFuncSetAttribute(router_kernel, cudaFuncAttributeMaxDynamicSharedMemorySize, SMEM_BYTES_R);

    uint32_t* xh = nullptr;  cudaGetSymbolAddress((void**)&xh,  g_xh);
    uint32_t* wih = nullptr; cudaGetSymbolAddress((void**)&wih, g_wih);
    uint32_t* woh = nullptr; cudaGetSymbolAddress((void**)&woh, g_woh);
    uint32_t* hc = nullptr;  cudaGetSymbolAddress((void**)&hc,  g_hcomb);

    conv_h<<<1024, 256>>>((const float4*)x,  (uint2*)xh,  T_TOK * DDIM / 4);
    conv_h<<<1024, 256>>>((const float4*)Wi, (uint2*)wih, FDIM * DDIM / 4);
    conv_h<<<1024, 256>>>((const float4*)Wo, (uint2*)woh, DDIM * FDIM / 4);

    router_kernel<<<T_TOK / 32, 512, SMEM_BYTES_R>>>(x, Wg, bg, A);

    gemm_h<0><<<dim3(FDIM / BN, T_TOK / BM), 256, SMEM_BYTES_G>>>(xh, wih, nullptr, DDIM / 2, Bm);
    gemm_h<1><<<dim3(DDIM / BN, T_TOK / BM), 256, SMEM_BYTES_G>>>(hc, woh, out, FDIM / 2, nullptr);
}

// round 12
// speedup vs baseline: 4.4507x; 1.2774x over previous
#include <cuda_runtime.h>
#include <cuda_fp16.h>
#include <cstdint>

// Problem shape (fixed by dataset)
#define T_TOK 4096   // B*S
#define DDIM  1024
#define FDIM  4096

// GEMM tiling (halves). BK = 64 halves = 32 words = 128 B/row.
#define BM 128
#define BN 128
#define BKW 32                           // 32-bit words of k per stage-row
#define LDS_PAD 36                       // words per smem row (32 + 4)
#define TILE_WORDS (128 * LDS_PAD)       // 4608 words per operand tile
#define STAGE_WORDS (2 * TILE_WORDS)
#define NSTAGE 3
#define SMEM_BYTES_G (NSTAGE * STAGE_WORDS * 4)   // 110592

// Router staging
#define RT_XW (32 * 36)                  // x floats per stage (32 tokens x 32k, pad 36)
#define RT_WW (20 * 36)                  // w floats per stage
#define RT_STG (RT_XW + RT_WW)           // 1872 floats per stage

// Scratch (static __device__ — no dynamic allocation allowed)
__device__ uint32_t g_xh[(size_t)T_TOK * DDIM / 2];    // x as half2 words, 8 MB
__device__ uint32_t g_wih[(size_t)FDIM * DDIM / 2];    // Wi as half2 words, 8 MB
__device__ uint32_t g_woh[(size_t)DDIM * FDIM / 2];    // Wo as half2 words, 8 MB
__device__ uint32_t g_hcomb[(size_t)T_TOK * FDIM / 2]; // hcomb as half2 words, 32 MB
__device__ float g_w[T_TOK * 4];
__device__ float g_low[T_TOK * 16];

__device__ __forceinline__ uint32_t smem_u32(const void* p) {
    uint32_t a;
    asm("{ .reg .u64 t; cvta.to.shared.u64 t, %1; cvt.u32.u64 %0, t; }" : "=r"(a) : "l"(p));
    return a;
}
__device__ __forceinline__ void mma_f16(float* c, const uint32_t* a, const uint32_t* b) {
    asm volatile("mma.sync.aligned.m16n8k16.row.col.f32.f16.f16.f32 "
                 "{%0,%1,%2,%3}, {%4,%5,%6,%7}, {%8,%9}, {%0,%1,%2,%3};"
                 : "+f"(c[0]), "+f"(c[1]), "+f"(c[2]), "+f"(c[3])
                 : "r"(a[0]), "r"(a[1]), "r"(a[2]), "r"(a[3]), "r"(b[0]), "r"(b[1]));
}
__device__ __forceinline__ uint32_t pack_h2(float lo, float hi) {
    __half2 h = __floats2half2_rn(lo, hi);
    return *(uint32_t*)&h;
}

// ---------------------------------------------------------------------------
// fp32 -> half2 conversion (used for Wi, Wo only; x is converted in router).
// ---------------------------------------------------------------------------
__global__ __launch_bounds__(256)
void conv_h(const float4* __restrict__ src, uint2* __restrict__ dst, int n4)
{
    int i = blockIdx.x * blockDim.x + threadIdx.x;
    int stride = gridDim.x * blockDim.x;
    for (; i < n4; i += stride) {
        float4 v = src[i];
        dst[i] = make_uint2(pack_h2(v.x, v.y), pack_h2(v.z, v.w));
    }
}

// ---------------------------------------------------------------------------
// Router v4: 128 blocks x 640 threads, 32 tokens/block. 3-stage cp.async
// pipeline over 32-float k chunks (x + weights). Thread = (token, j) with a
// SCALAR accumulator (no spills). Also converts x -> g_xh (half2) in-flight.
// ---------------------------------------------------------------------------
__device__ __forceinline__ void rt_issue(uint32_t base, const float* __restrict__ x,
                                         const float* __restrict__ Wg,
                                         const float* __restrict__ A,
                                         int t0, int k0, int tid)
{
    if (tid < 256) {            // x chunk: 32 tokens x 128 B
        int row = tid >> 3, cc = tid & 7;
        uint32_t off = base + (uint32_t)(row * 36 + cc * 4) * 4;
        const void* g = x + (size_t)(t0 + row) * DDIM + k0 + cc * 4;
        asm volatile("cp.async.cg.shared.global [%0], [%1], 16;" :: "r"(off), "l"(g));
    } else if (tid < 416) {     // weight chunk: 20 rows x 128 B
        int i = tid - 256, row = i >> 3, cc = i & 7;
        const float* src = (row < 4) ? (Wg + (size_t)row * DDIM)
                                     : (A + (size_t)(row - 4) * DDIM);
        uint32_t off = base + (uint32_t)RT_XW * 4 + (uint32_t)(row * 36 + cc * 4) * 4;
        asm volatile("cp.async.cg.shared.global [%0], [%1], 16;" :: "r"(off), "l"(src + k0 + cc * 4));
    }
    asm volatile("cp.async.commit_group;");
}

__global__ __launch_bounds__(640)
void router_kernel(const float* __restrict__ x, const float* __restrict__ Wg,
                   const float* __restrict__ bg, const float* __restrict__ A)
{
    __shared__ float sm[3 * RT_STG];
    __shared__ float ps[32 * 20];
    const uint32_t sb = smem_u32(sm);
    const int tid = threadIdx.x;
    const int t0 = blockIdx.x * 32;
    const int tok = tid / 20, j = tid % 20;       // tid < 640 => tok 0..31

    float acc = 0.f;
    const int nChunk = DDIM / 32;                  // 32

    rt_issue(sb, x, Wg, A, t0, 0, tid);
    rt_issue(sb + RT_STG * 4, x, Wg, A, t0, 32, tid);

    for (int c = 0; c < nChunk; c++) {
        if (c + 2 < nChunk) {
            asm volatile("cp.async.wait_group 1;");
        } else {
            asm volatile("cp.async.wait_group 0;");
        }
        __syncthreads();

        if (c + 2 < nChunk) {
            int wbuf = c + 2; while (wbuf >= 3) wbuf -= 3;
            rt_issue(sb + (uint32_t)(wbuf * RT_STG) * 4, x, Wg, A, t0, (c + 2) * 32, tid);
        }

        int buf = c; while (buf >= 3) buf -= 3;
        const float* xs = sm + buf * RT_STG;
        const float* ws = xs + RT_XW;

        // dot-product contribution for this chunk
#pragma unroll
        for (int k4 = 0; k4 < 8; k4++) {
            float4 xv = *(const float4*)&xs[tok * 36 + k4 * 4];
            float4 wv = *(const float4*)&ws[j * 36 + k4 * 4];
            acc += xv.x * wv.x + xv.y * wv.y + xv.z * wv.z + xv.w * wv.w;
        }

        // convert this x chunk to half2 -> g_xh (512 half2 words per chunk)
        if (tid < 512) {
            int tk = tid >> 4, h = tid & 15;
            float lo = xs[tk * 36 + h * 2];
            float hi = xs[tk * 36 + h * 2 + 1];
            g_xh[(size_t)(t0 + tk) * (DDIM / 2) + c * 16 + h] = pack_h2(lo, hi);
        }
    }

    ps[tid] = acc;
    __syncthreads();

    if (tid < 32) {
        int t = t0 + tid;
        float l[4];
#pragma unroll
        for (int e = 0; e < 4; e++) l[e] = ps[tid * 20 + e] + bg[e];
        float m = fmaxf(fmaxf(l[0], l[1]), fmaxf(l[2], l[3]));
        float p[4], s = 0.f;
#pragma unroll
        for (int e = 0; e < 4; e++) { p[e] = expf(l[e] - m); s += p[e]; }
        float inv = 1.f / s;
#pragma unroll
        for (int e = 0; e < 4; e++) p[e] *= inv;
        int i1 = 0; float b1 = p[0];
#pragma unroll
        for (int e = 1; e < 4; e++) if (p[e] > b1) { b1 = p[e]; i1 = e; }
        int i2 = -1; float b2 = -1.f;
#pragma unroll
        for (int e = 0; e < 4; e++) if (e != i1 && p[e] > b2) { b2 = p[e]; i2 = e; }
#pragma unroll
        for (int e = 0; e < 4; e++)
            g_w[t * 4 + e] = (e == i1 || e == i2) ? p[e] : 0.f;
#pragma unroll
        for (int i = 0; i < 16; i++)
            g_low[t * 16 + i] = ps[tid * 20 + 4 + i];
    }
}

// ---------------------------------------------------------------------------
// FP16 mma.sync m16n8k16 TN GEMM, 3-stage cp.async pipeline, 1 sync/iter.
// (unchanged from R11 — proven at 516us total)
// ---------------------------------------------------------------------------
__device__ __forceinline__ void issue_tile(uint32_t sbaseA, const uint32_t* __restrict__ Ag,
                                           uint32_t sbaseB, const uint32_t* __restrict__ Bg,
                                           int Kw, int k0w, int tid)
{
#pragma unroll
    for (int t = 0; t < 4; t++) {           // 1024 chunks: 128 rows x 8 chunks
        int idx = tid + t * 256;
        int row = idx >> 3, c4 = idx & 7;
        uint32_t off = (uint32_t)(row * LDS_PAD + c4 * 4) * 4;
        const void* ga = Ag + (size_t)row * Kw + k0w + c4 * 4;
        const void* gb = Bg + (size_t)row * Kw + k0w + c4 * 4;
        asm volatile("cp.async.cg.shared.global [%0], [%1], 16;" :: "r"(sbaseA + off), "l"(ga));
        asm volatile("cp.async.cg.shared.global [%0], [%1], 16;" :: "r"(sbaseB + off), "l"(gb));
    }
}

template <int MODE>
__global__ __launch_bounds__(256, 2)
void gemm_h(const uint32_t* __restrict__ Ain, const uint32_t* __restrict__ Bin,
            float* __restrict__ Cout, int Kw, const float* __restrict__ pBm)
{
    extern __shared__ uint32_t smem[];
    const uint32_t sb = smem_u32(smem);
    const int tid = threadIdx.x;
    const int wid = tid >> 5, lane = tid & 31;
    const int g = lane >> 2, q = lane & 3;
    const int wm = wid & 3, wn = wid >> 2;
    const int m0 = blockIdx.y * BM;
    const int n0 = blockIdx.x * BN;

    const uint32_t* Aptr = Ain + (size_t)m0 * Kw;
    const uint32_t* Bptr = Bin + (size_t)n0 * Kw;

    float acc[2][8][4];
#pragma unroll
    for (int mt = 0; mt < 2; mt++)
#pragma unroll
        for (int nt = 0; nt < 8; nt++)
#pragma unroll
            for (int e = 0; e < 4; e++) acc[mt][nt][e] = 0.f;

    const int nIter = Kw / BKW;

    issue_tile(sb, Aptr, sb + TILE_WORDS * 4, Bptr, Kw, 0, tid);
    asm volatile("cp.async.commit_group;");
    issue_tile(sb + STAGE_WORDS * 4, Aptr, sb + (STAGE_WORDS + TILE_WORDS) * 4, Bptr, Kw, BKW, tid);
    asm volatile("cp.async.commit_group;");

    int buf = 0;
    for (int i = 0; i < nIter; i++) {
        if (i + 2 < nIter) {
            asm volatile("cp.async.wait_group 1;");
        } else {
            asm volatile("cp.async.wait_group 0;");
        }
        __syncthreads();

        if (i + 2 < nIter) {
            int wbuf = buf + 2; if (wbuf >= NSTAGE) wbuf -= NSTAGE;
            uint32_t wb = sb + (uint32_t)(wbuf * STAGE_WORDS) * 4;
            issue_tile(wb, Aptr, wb + TILE_WORDS * 4, Bptr, Kw, (i + 2) * BKW, tid);
            asm volatile("cp.async.commit_group;");
        }

        const uint32_t* As = smem + buf * STAGE_WORDS;
        const uint32_t* Bs = As + TILE_WORDS;
#pragma unroll
        for (int kk = 0; kk < 4; kk++) {          // each kk = 16 halves of k
            uint32_t a[2][4];
#pragma unroll
            for (int mt = 0; mt < 2; mt++) {
                int mrow = wm * 32 + mt * 16 + g;
                a[mt][0] = As[mrow * LDS_PAD + kk * 8 + q];
                a[mt][1] = As[(mrow + 8) * LDS_PAD + kk * 8 + q];
                a[mt][2] = As[mrow * LDS_PAD + kk * 8 + q + 4];
                a[mt][3] = As[(mrow + 8) * LDS_PAD + kk * 8 + q + 4];
            }
#pragma unroll
            for (int nt = 0; nt < 8; nt++) {
                int nrow = wn * 64 + nt * 8 + g;
                uint32_t b[2];
                b[0] = Bs[nrow * LDS_PAD + kk * 8 + q];
                b[1] = Bs[nrow * LDS_PAD + kk * 8 + q + 4];
#pragma unroll
                for (int mt = 0; mt < 2; mt++)
                    mma_f16(acc[mt][nt], a[mt], b);
            }
        }
        if (++buf >= NSTAGE) buf = 0;
    }
    __syncthreads();     // all MMA reads done before smem reuse by epilogue

    if (MODE == 0) {
        // Fused MoE epilogue: hcomb = sum_e w_e * relu(base + low_e . Bm_e)
        float* w_s   = (float*)&smem[0];       // [128][4]
        float* low_s = (float*)&smem[512];     // [128][16]
        float* bm_s  = (float*)&smem[2560];    // [4][128][4]
        for (int i = tid; i < 128 * 4; i += 256)
            w_s[i] = g_w[(size_t)(m0 + (i >> 2)) * 4 + (i & 3)];
        for (int i = tid; i < 128 * 16; i += 256)
            low_s[i] = g_low[(size_t)(m0 + (i >> 4)) * 16 + (i & 15)];
        for (int i = tid; i < 4 * 128 * 4; i += 256) {
            int e = i >> 9, f = (i >> 2) & 127, r = i & 3;
            bm_s[i] = pBm[(size_t)e * (FDIM * 4) + (size_t)(n0 + f) * 4 + r];
        }
        __syncthreads();

#pragma unroll
        for (int mt = 0; mt < 2; mt++) {
#pragma unroll
            for (int half = 0; half < 2; half++) {
                int r = wm * 32 + mt * 16 + g + half * 8;     // local row
                float4 wv = *(const float4*)&w_s[r * 4];
                float4 lv[4];
#pragma unroll
                for (int e = 0; e < 4; e++) lv[e] = *(const float4*)&low_s[r * 16 + e * 4];
                uint32_t* dst = g_hcomb + (size_t)(m0 + r) * (FDIM / 2) + n0 / 2;
#pragma unroll
                for (int nt = 0; nt < 8; nt++) {
                    int cl = wn * 64 + nt * 8 + 2 * q;        // even column
                    float o[2];
#pragma unroll
                    for (int j = 0; j < 2; j++) {
                        float base = acc[mt][nt][half * 2 + j];
                        int col = cl + j;
                        float h = 0.f;
#pragma unroll
                        for (int e = 0; e < 4; e++) {
                            float4 bm = *(const float4*)&bm_s[(e * 128 + col) * 4];
                            float lo = lv[e].x * bm.x + lv[e].y * bm.y
                                     + lv[e].z * bm.z + lv[e].w * bm.w;
                            float wcomp = (e == 0) ? wv.x : (e == 1) ? wv.y
                                        : (e == 2) ? wv.z : wv.w;
                            h = fmaf(wcomp, fmaxf(base + lo, 0.f), h);
                        }
                        o[j] = h;
                    }
                    dst[cl >> 1] = pack_h2(o[0], o[1]);
                }
            }
        }
    } else {
#pragma unroll
        for (int mt = 0; mt < 2; mt++) {
#pragma unroll
            for (int half = 0; half < 2; half++) {
                int r = wm * 32 + mt * 16 + g + half * 8;
                float* dst = Cout + (size_t)(m0 + r) * DDIM + n0;
#pragma unroll
                for (int nt = 0; nt < 8; nt++) {
                    int cl = wn * 64 + nt * 8 + 2 * q;
                    *(float2*)(dst + cl) =
                        make_float2(acc[mt][nt][half * 2], acc[mt][nt][half * 2 + 1]);
                }
            }
        }
    }
}

// ---------------------------------------------------------------------------
extern "C" void kernel_launch(void* const* d_in, const int* in_sizes, int n_in,
                              void* d_out, int out_size)
{
    const float* x  = (const float*)d_in[0];
    const float* Wg = (const float*)d_in[1];
    const float* bg = (const float*)d_in[2];
    const float* Wi = (const float*)d_in[3];
    const float* Wo = (const float*)d_in[4];
    const float* A  = (const float*)d_in[5];
    const float* Bm = (const float*)d_in[6];
    float* out = (float*)d_out;

    cudaFuncSetAttribute(gemm_h<0>, cudaFuncAttributeMaxDynamicSharedMemorySize, SMEM_BYTES_G);
    cudaFuncSetAttribute(gemm_h<1>, cudaFuncAttributeMaxDynamicSharedMemorySize, SMEM_BYTES_G);

    uint32_t* xh = nullptr;  cudaGetSymbolAddress((void**)&xh,  g_xh);
    uint32_t* wih = nullptr; cudaGetSymbolAddress((void**)&wih, g_wih);
    uint32_t* woh = nullptr; cudaGetSymbolAddress((void**)&woh, g_woh);
    uint32_t* hc = nullptr;  cudaGetSymbolAddress((void**)&hc,  g_hcomb);

    conv_h<<<1024, 256>>>((const float4*)Wi, (uint2*)wih, FDIM * DDIM / 4);
    conv_h<<<1024, 256>>>((const float4*)Wo, (uint2*)woh, DDIM * FDIM / 4);

    router_kernel<<<T_TOK / 32, 640>>>(x, Wg, bg, A);   // also writes g_xh

    gemm_h<0><<<dim3(FDIM / BN, T_TOK / BM), 256, SMEM_BYTES_G>>>(xh, wih, nullptr, DDIM / 2, Bm);
    gemm_h<1><<<dim3(DDIM / BN, T_TOK / BM), 256, SMEM_BYTES_G>>>(hc, woh, out, FDIM / 2, nullptr);
}

// round 13
// speedup vs baseline: 4.6454x; 1.0437x over previous
#include <cuda_runtime.h>
#include <cuda_fp16.h>
#include <cstdint>

// Problem shape (fixed by dataset)
#define T_TOK 4096   // B*S
#define DDIM  1024
#define FDIM  4096

// GEMM tiling (halves). BK = 64 halves = 32 words = 128 B/row.
#define BM 128
#define BN 128
#define BKW 32                           // 32-bit words of k per stage-row
#define LDS_PAD 36                       // words per smem row (32 + 4) -> 144 B
#define TILE_WORDS (128 * LDS_PAD)       // 4608 words per operand tile
#define STAGE_WORDS (2 * TILE_WORDS)
#define NSTAGE 3
#define SMEM_BYTES_G (NSTAGE * STAGE_WORDS * 4)   // 110592

// Router staging
#define RT_XW (32 * 36)
#define RT_WW (20 * 36)
#define RT_STG (RT_XW + RT_WW)

// Scratch (static __device__ — no dynamic allocation allowed)
__device__ uint32_t g_xh[(size_t)T_TOK * DDIM / 2];    // x as half2 words, 8 MB
__device__ uint32_t g_wih[(size_t)FDIM * DDIM / 2];    // Wi as half2 words, 8 MB
__device__ uint32_t g_woh[(size_t)DDIM * FDIM / 2];    // Wo as half2 words, 8 MB
__device__ uint32_t g_hcomb[(size_t)T_TOK * FDIM / 2]; // hcomb as half2 words, 32 MB
__device__ float g_w[T_TOK * 4];
__device__ float g_low[T_TOK * 16];

__device__ __forceinline__ uint32_t smem_u32(const void* p) {
    uint32_t a;
    asm("{ .reg .u64 t; cvta.to.shared.u64 t, %1; cvt.u32.u64 %0, t; }" : "=r"(a) : "l"(p));
    return a;
}
__device__ __forceinline__ void mma_f16(float* c, const uint32_t* a, const uint32_t* b) {
    asm volatile("mma.sync.aligned.m16n8k16.row.col.f32.f16.f16.f32 "
                 "{%0,%1,%2,%3}, {%4,%5,%6,%7}, {%8,%9}, {%0,%1,%2,%3};"
                 : "+f"(c[0]), "+f"(c[1]), "+f"(c[2]), "+f"(c[3])
                 : "r"(a[0]), "r"(a[1]), "r"(a[2]), "r"(a[3]), "r"(b[0]), "r"(b[1]));
}
__device__ __forceinline__ void ldm_x4(uint32_t* r, uint32_t addr) {
    asm volatile("ldmatrix.sync.aligned.m8n8.x4.shared.b16 {%0,%1,%2,%3}, [%4];"
                 : "=r"(r[0]), "=r"(r[1]), "=r"(r[2]), "=r"(r[3]) : "r"(addr));
}
__device__ __forceinline__ uint32_t pack_h2(float lo, float hi) {
    __half2 h = __floats2half2_rn(lo, hi);
    return *(uint32_t*)&h;
}

// ---------------------------------------------------------------------------
// fp32 -> half2 conversion (Wi, Wo only; x converted inside the router).
// ---------------------------------------------------------------------------
__global__ __launch_bounds__(256)
void conv_h(const float4* __restrict__ src, uint2* __restrict__ dst, int n4)
{
    int i = blockIdx.x * blockDim.x + threadIdx.x;
    int stride = gridDim.x * blockDim.x;
    for (; i < n4; i += stride) {
        float4 v = src[i];
        dst[i] = make_uint2(pack_h2(v.x, v.y), pack_h2(v.z, v.w));
    }
}

// ---------------------------------------------------------------------------
// Router: 128 blocks x 640 threads, 32 tokens/block, 3-stage cp.async pipe.
// Thread = (token, j), scalar accumulator. Also emits g_xh (half2).
// ---------------------------------------------------------------------------
__device__ __forceinline__ void rt_issue(uint32_t base, const float* __restrict__ x,
                                         const float* __restrict__ Wg,
                                         const float* __restrict__ A,
                                         int t0, int k0, int tid)
{
    if (tid < 256) {            // x chunk: 32 tokens x 128 B
        int row = tid >> 3, cc = tid & 7;
        uint32_t off = base + (uint32_t)(row * 36 + cc * 4) * 4;
        const void* g = x + (size_t)(t0 + row) * DDIM + k0 + cc * 4;
        asm volatile("cp.async.cg.shared.global [%0], [%1], 16;" :: "r"(off), "l"(g));
    } else if (tid < 416) {     // weight chunk: 20 rows x 128 B
        int i = tid - 256, row = i >> 3, cc = i & 7;
        const float* src = (row < 4) ? (Wg + (size_t)row * DDIM)
                                     : (A + (size_t)(row - 4) * DDIM);
        uint32_t off = base + (uint32_t)RT_XW * 4 + (uint32_t)(row * 36 + cc * 4) * 4;
        asm volatile("cp.async.cg.shared.global [%0], [%1], 16;" :: "r"(off), "l"(src + k0 + cc * 4));
    }
    asm volatile("cp.async.commit_group;");
}

__global__ __launch_bounds__(640)
void router_kernel(const float* __restrict__ x, const float* __restrict__ Wg,
                   const float* __restrict__ bg, const float* __restrict__ A)
{
    __shared__ float sm[3 * RT_STG];
    __shared__ float ps[32 * 20];
    const uint32_t sb = smem_u32(sm);
    const int tid = threadIdx.x;
    const int t0 = blockIdx.x * 32;
    const int tok = tid / 20, j = tid % 20;

    float acc = 0.f;
    const int nChunk = DDIM / 32;

    rt_issue(sb, x, Wg, A, t0, 0, tid);
    rt_issue(sb + RT_STG * 4, x, Wg, A, t0, 32, tid);

    for (int c = 0; c < nChunk; c++) {
        if (c + 2 < nChunk) {
            asm volatile("cp.async.wait_group 1;");
        } else {
            asm volatile("cp.async.wait_group 0;");
        }
        __syncthreads();

        if (c + 2 < nChunk) {
            int wbuf = c + 2; while (wbuf >= 3) wbuf -= 3;
            rt_issue(sb + (uint32_t)(wbuf * RT_STG) * 4, x, Wg, A, t0, (c + 2) * 32, tid);
        }

        int buf = c; while (buf >= 3) buf -= 3;
        const float* xs = sm + buf * RT_STG;
        const float* ws = xs + RT_XW;

#pragma unroll
        for (int k4 = 0; k4 < 8; k4++) {
            float4 xv = *(const float4*)&xs[tok * 36 + k4 * 4];
            float4 wv = *(const float4*)&ws[j * 36 + k4 * 4];
            acc += xv.x * wv.x + xv.y * wv.y + xv.z * wv.z + xv.w * wv.w;
        }

        if (tid < 512) {
            int tk = tid >> 4, h = tid & 15;
            float lo = xs[tk * 36 + h * 2];
            float hi = xs[tk * 36 + h * 2 + 1];
            g_xh[(size_t)(t0 + tk) * (DDIM / 2) + c * 16 + h] = pack_h2(lo, hi);
        }
    }

    ps[tid] = acc;
    __syncthreads();

    if (tid < 32) {
        int t = t0 + tid;
        float l[4];
#pragma unroll
        for (int e = 0; e < 4; e++) l[e] = ps[tid * 20 + e] + bg[e];
        float m = fmaxf(fmaxf(l[0], l[1]), fmaxf(l[2], l[3]));
        float p[4], s = 0.f;
#pragma unroll
        for (int e = 0; e < 4; e++) { p[e] = expf(l[e] - m); s += p[e]; }
        float inv = 1.f / s;
#pragma unroll
        for (int e = 0; e < 4; e++) p[e] *= inv;
        int i1 = 0; float b1 = p[0];
#pragma unroll
        for (int e = 1; e < 4; e++) if (p[e] > b1) { b1 = p[e]; i1 = e; }
        int i2 = -1; float b2 = -1.f;
#pragma unroll
        for (int e = 0; e < 4; e++) if (e != i1 && p[e] > b2) { b2 = p[e]; i2 = e; }
#pragma unroll
        for (int e = 0; e < 4; e++)
            g_w[t * 4 + e] = (e == i1 || e == i2) ? p[e] : 0.f;
#pragma unroll
        for (int i = 0; i < 16; i++)
            g_low[t * 16 + i] = ps[tid * 20 + 4 + i];
    }
}

// ---------------------------------------------------------------------------
// FP16 mma.sync m16n8k16 TN GEMM, 3-stage cp.async pipeline, ldmatrix
// fragment loads (bit-identical layout to the former scalar loads).
// ---------------------------------------------------------------------------
__device__ __forceinline__ void issue_tile(uint32_t sbaseA, const uint32_t* __restrict__ Ag,
                                           uint32_t sbaseB, const uint32_t* __restrict__ Bg,
                                           int Kw, int k0w, int tid)
{
#pragma unroll
    for (int t = 0; t < 4; t++) {           // 1024 chunks: 128 rows x 8 chunks
        int idx = tid + t * 256;
        int row = idx >> 3, c4 = idx & 7;
        uint32_t off = (uint32_t)(row * LDS_PAD + c4 * 4) * 4;
        const void* ga = Ag + (size_t)row * Kw + k0w + c4 * 4;
        const void* gb = Bg + (size_t)row * Kw + k0w + c4 * 4;
        asm volatile("cp.async.cg.shared.global [%0], [%1], 16;" :: "r"(sbaseA + off), "l"(ga));
        asm volatile("cp.async.cg.shared.global [%0], [%1], 16;" :: "r"(sbaseB + off), "l"(gb));
    }
}

template <int MODE>
__global__ __launch_bounds__(256, 2)
void gemm_h(const uint32_t* __restrict__ Ain, const uint32_t* __restrict__ Bin,
            float* __restrict__ Cout, int Kw, const float* __restrict__ pBm)
{
    extern __shared__ uint32_t smem[];
    const uint32_t sb = smem_u32(smem);
    const int tid = threadIdx.x;
    const int wid = tid >> 5, lane = tid & 31;
    const int g = lane >> 2, q = lane & 3;
    const int wm = wid & 3, wn = wid >> 2;
    const int m0 = blockIdx.y * BM;
    const int n0 = blockIdx.x * BN;

    const uint32_t* Aptr = Ain + (size_t)m0 * Kw;
    const uint32_t* Bptr = Bin + (size_t)n0 * Kw;

    // per-thread ldmatrix base byte-offsets (row stride = 144 B)
    // A (x4): lanes 0-7 rows0-7 k0-7 | 8-15 rows8-15 k0-7 | 16-23 rows0-7 k8-15 | 24-31 rows8-15 k8-15
    uint32_t a_base[2];
#pragma unroll
    for (int mt = 0; mt < 2; mt++) {
        int row = wm * 32 + mt * 16 + (lane & 15);
        a_base[mt] = (uint32_t)(row * (LDS_PAD * 4)) + ((lane >> 4) * 16);
    }
    // B (x4, two n-tiles): lanes 0-7 n0-7 k0-7 | 8-15 n0-7 k8-15 | 16-23 n8-15 k0-7 | 24-31 n8-15 k8-15
    uint32_t b_base[4];
#pragma unroll
    for (int ntp = 0; ntp < 4; ntp++) {
        int nrow = wn * 64 + ntp * 16 + (lane & 7) + ((lane & 16) ? 8 : 0);
        b_base[ntp] = (uint32_t)(TILE_WORDS * 4) + (uint32_t)(nrow * (LDS_PAD * 4))
                    + (((lane >> 3) & 1) * 16);
    }

    float acc[2][8][4];
#pragma unroll
    for (int mt = 0; mt < 2; mt++)
#pragma unroll
        for (int nt = 0; nt < 8; nt++)
#pragma unroll
            for (int e = 0; e < 4; e++) acc[mt][nt][e] = 0.f;

    const int nIter = Kw / BKW;

    issue_tile(sb, Aptr, sb + TILE_WORDS * 4, Bptr, Kw, 0, tid);
    asm volatile("cp.async.commit_group;");
    issue_tile(sb + STAGE_WORDS * 4, Aptr, sb + (STAGE_WORDS + TILE_WORDS) * 4, Bptr, Kw, BKW, tid);
    asm volatile("cp.async.commit_group;");

    int buf = 0;
    for (int i = 0; i < nIter; i++) {
        if (i + 2 < nIter) {
            asm volatile("cp.async.wait_group 1;");
        } else {
            asm volatile("cp.async.wait_group 0;");
        }
        __syncthreads();

        if (i + 2 < nIter) {
            int wbuf = buf + 2; if (wbuf >= NSTAGE) wbuf -= NSTAGE;
            uint32_t wb = sb + (uint32_t)(wbuf * STAGE_WORDS) * 4;
            issue_tile(wb, Aptr, wb + TILE_WORDS * 4, Bptr, Kw, (i + 2) * BKW, tid);
            asm volatile("cp.async.commit_group;");
        }

        const uint32_t sbuf = sb + (uint32_t)(buf * STAGE_WORDS) * 4;
#pragma unroll
        for (int kk = 0; kk < 4; kk++) {          // each kk = 16 halves of k
            const uint32_t koff = (uint32_t)(kk * 32);
            uint32_t a[2][4];
            ldm_x4(a[0], sbuf + a_base[0] + koff);
            ldm_x4(a[1], sbuf + a_base[1] + koff);
#pragma unroll
            for (int ntp = 0; ntp < 4; ntp++) {
                uint32_t b[4];                     // {b0,b1} of nt=2*ntp, {b0,b1} of nt=2*ntp+1
                ldm_x4(b, sbuf + b_base[ntp] + koff);
#pragma unroll
                for (int mt = 0; mt < 2; mt++) {
                    mma_f16(acc[mt][2 * ntp],     a[mt], b);
                    mma_f16(acc[mt][2 * ntp + 1], a[mt], b + 2);
                }
            }
        }
        if (++buf >= NSTAGE) buf = 0;
    }
    __syncthreads();     // all MMA reads done before smem reuse by epilogue

    if (MODE == 0) {
        // Fused MoE epilogue: hcomb = sum_e w_e * relu(base + low_e . Bm_e)
        float* w_s   = (float*)&smem[0];       // [128][4]
        float* low_s = (float*)&smem[512];     // [128][16]
        float* bm_s  = (float*)&smem[2560];    // [4][128][4]
        for (int i = tid; i < 128 * 4; i += 256)
            w_s[i] = g_w[(size_t)(m0 + (i >> 2)) * 4 + (i & 3)];
        for (int i = tid; i < 128 * 16; i += 256)
            low_s[i] = g_low[(size_t)(m0 + (i >> 4)) * 16 + (i & 15)];
        for (int i = tid; i < 4 * 128 * 4; i += 256) {
            int e = i >> 9, f = (i >> 2) & 127, r = i & 3;
            bm_s[i] = pBm[(size_t)e * (FDIM * 4) + (size_t)(n0 + f) * 4 + r];
        }
        __syncthreads();

#pragma unroll
        for (int mt = 0; mt < 2; mt++) {
#pragma unroll
            for (int half = 0; half < 2; half++) {
                int r = wm * 32 + mt * 16 + g + half * 8;     // local row
                float4 wv = *(const float4*)&w_s[r * 4];
                float4 lv[4];
#pragma unroll
                for (int e = 0; e < 4; e++) lv[e] = *(const float4*)&low_s[r * 16 + e * 4];
                uint32_t* dst = g_hcomb + (size_t)(m0 + r) * (FDIM / 2) + n0 / 2;
#pragma unroll
                for (int nt = 0; nt < 8; nt++) {
                    int cl = wn * 64 + nt * 8 + 2 * q;        // even column
                    float o[2];
#pragma unroll
                    for (int j = 0; j < 2; j++) {
                        float base = acc[mt][nt][half * 2 + j];
                        int col = cl + j;
                        float h = 0.f;
#pragma unroll
                        for (int e = 0; e < 4; e++) {
                            float4 bm = *(const float4*)&bm_s[(e * 128 + col) * 4];
                            float lo = lv[e].x * bm.x + lv[e].y * bm.y
                                     + lv[e].z * bm.z + lv[e].w * bm.w;
                            float wcomp = (e == 0) ? wv.x : (e == 1) ? wv.y
                                        : (e == 2) ? wv.z : wv.w;
                            h = fmaf(wcomp, fmaxf(base + lo, 0.f), h);
                        }
                        o[j] = h;
                    }
                    dst[cl >> 1] = pack_h2(o[0], o[1]);
                }
            }
        }
    } else {
#pragma unroll
        for (int mt = 0; mt < 2; mt++) {
#pragma unroll
            for (int half = 0; half < 2; half++) {
                int r = wm * 32 + mt * 16 + g + half * 8;
                float* dst = Cout + (size_t)(m0 + r) * DDIM + n0;
#pragma unroll
                for (int nt = 0; nt < 8; nt++) {
                    int cl = wn * 64 + nt * 8 + 2 * q;
                    *(float2*)(dst + cl) =
                        make_float2(acc[mt][nt][half * 2], acc[mt][nt][half * 2 + 1]);
                }
            }
        }
    }
}

// ---------------------------------------------------------------------------
extern "C" void kernel_launch(void* const* d_in, const int* in_sizes, int n_in,
                              void* d_out, int out_size)
{
    const float* x  = (const float*)d_in[0];
    const float* Wg = (const float*)d_in[1];
    const float* bg = (const float*)d_in[2];
    const float* Wi = (const float*)d_in[3];
    const float* Wo = (const float*)d_in[4];
    const float* A  = (const float*)d_in[5];
    const float* Bm = (const float*)d_in[6];
    float* out = (float*)d_out;

    cudaFuncSetAttribute(gemm_h<0>, cudaFuncAttributeMaxDynamicSharedMemorySize, SMEM_BYTES_G);
    cudaFuncSetAttribute(gemm_h<1>, cudaFuncAttributeMaxDynamicSharedMemorySize, SMEM_BYTES_G);

    uint32_t* xh = nullptr;  cudaGetSymbolAddress((void**)&xh,  g_xh);
    uint32_t* wih = nullptr; cudaGetSymbolAddress((void**)&wih, g_wih);
    uint32_t* woh = nullptr; cudaGetSymbolAddress((void**)&woh, g_woh);
    uint32_t* hc = nullptr;  cudaGetSymbolAddress((void**)&hc,  g_hcomb);

    conv_h<<<1024, 256>>>((const float4*)Wi, (uint2*)wih, FDIM * DDIM / 4);
    conv_h<<<1024, 256>>>((const float4*)Wo, (uint2*)woh, DDIM * FDIM / 4);

    router_kernel<<<T_TOK / 32, 640>>>(x, Wg, bg, A);   // also writes g_xh

    gemm_h<0><<<dim3(FDIM / BN, T_TOK / BM), 256, SMEM_BYTES_G>>>(xh, wih, nullptr, DDIM / 2, Bm);
    gemm_h<1><<<dim3(DDIM / BN, T_TOK / BM), 256, SMEM_BYTES_G>>>(hc, woh, out, FDIM / 2, nullptr);
}

// round 14
// speedup vs baseline: 6.1409x; 1.3219x over previous
#include <cuda_runtime.h>
#include <cuda_fp16.h>
#include <cstdint>

// Problem shape (fixed by dataset)
#define T_TOK 4096   // B*S
#define DDIM  1024
#define FDIM  4096

// GEMM tiling (halves). BK = 64 halves = 32 words = 128 B/row.
#define BM 128
#define BN 128
#define BKW 32                           // 32-bit words of k per stage-row
#define LDS_PAD 36                       // words per smem row (32 + 4) -> 144 B
#define TILE_WORDS (128 * LDS_PAD)       // 4608 words per operand tile
#define STAGE_WORDS (2 * TILE_WORDS)
#define NSTAGE 3
#define SMEM_BYTES_G (NSTAGE * STAGE_WORDS * 4)   // 110592

// Router staging
#define RT_XW (32 * 36)
#define RT_WW (20 * 36)
#define RT_STG (RT_XW + RT_WW)

// Scratch (static __device__ — no dynamic allocation allowed)
__device__ uint32_t g_xh[(size_t)T_TOK * DDIM / 2];    // x as half2 words, 8 MB
__device__ uint32_t g_wih[(size_t)FDIM * DDIM / 2];    // Wi as half2 words, 8 MB
__device__ uint32_t g_woh[(size_t)DDIM * FDIM / 2];    // Wo as half2 words, 8 MB
__device__ uint32_t g_hcomb[(size_t)T_TOK * FDIM / 2]; // hcomb as half2 words, 32 MB
__device__ float4 g_top[T_TOK];                        // (w1, w2, i1(bits), i2(bits))
__device__ float g_low[T_TOK * 16];

__device__ __forceinline__ uint32_t smem_u32(const void* p) {
    uint32_t a;
    asm("{ .reg .u64 t; cvta.to.shared.u64 t, %1; cvt.u32.u64 %0, t; }" : "=r"(a) : "l"(p));
    return a;
}
__device__ __forceinline__ void mma_f16(float* c, const uint32_t* a, const uint32_t* b) {
    asm volatile("mma.sync.aligned.m16n8k16.row.col.f32.f16.f16.f32 "
                 "{%0,%1,%2,%3}, {%4,%5,%6,%7}, {%8,%9}, {%0,%1,%2,%3};"
                 : "+f"(c[0]), "+f"(c[1]), "+f"(c[2]), "+f"(c[3])
                 : "r"(a[0]), "r"(a[1]), "r"(a[2]), "r"(a[3]), "r"(b[0]), "r"(b[1]));
}
__device__ __forceinline__ void ldm_x4(uint32_t* r, uint32_t addr) {
    asm volatile("ldmatrix.sync.aligned.m8n8.x4.shared.b16 {%0,%1,%2,%3}, [%4];"
                 : "=r"(r[0]), "=r"(r[1]), "=r"(r[2]), "=r"(r[3]) : "r"(addr));
}
__device__ __forceinline__ uint32_t pack_h2(float lo, float hi) {
    __half2 h = __floats2half2_rn(lo, hi);
    return *(uint32_t*)&h;
}

// ---------------------------------------------------------------------------
// fp32 -> half2 conversion (Wi, Wo only; x converted inside the router).
// ---------------------------------------------------------------------------
__global__ __launch_bounds__(256)
void conv_h(const float4* __restrict__ src, uint2* __restrict__ dst, int n4)
{
    int i = blockIdx.x * blockDim.x + threadIdx.x;
    int stride = gridDim.x * blockDim.x;
    for (; i < n4; i += stride) {
        float4 v = src[i];
        dst[i] = make_uint2(pack_h2(v.x, v.y), pack_h2(v.z, v.w));
    }
}

// ---------------------------------------------------------------------------
// Router: 128 blocks x 640 threads, 32 tokens/block, 3-stage cp.async pipe.
// Thread = (token, j), scalar accumulator. Emits g_xh (half2), g_top, g_low.
// ---------------------------------------------------------------------------
__device__ __forceinline__ void rt_issue(uint32_t base, const float* __restrict__ x,
                                         const float* __restrict__ Wg,
                                         const float* __restrict__ A,
                                         int t0, int k0, int tid)
{
    if (tid < 256) {            // x chunk: 32 tokens x 128 B
        int row = tid >> 3, cc = tid & 7;
        uint32_t off = base + (uint32_t)(row * 36 + cc * 4) * 4;
        const void* g = x + (size_t)(t0 + row) * DDIM + k0 + cc * 4;
        asm volatile("cp.async.cg.shared.global [%0], [%1], 16;" :: "r"(off), "l"(g));
    } else if (tid < 416) {     // weight chunk: 20 rows x 128 B
        int i = tid - 256, row = i >> 3, cc = i & 7;
        const float* src = (row < 4) ? (Wg + (size_t)row * DDIM)
                                     : (A + (size_t)(row - 4) * DDIM);
        uint32_t off = base + (uint32_t)RT_XW * 4 + (uint32_t)(row * 36 + cc * 4) * 4;
        asm volatile("cp.async.cg.shared.global [%0], [%1], 16;" :: "r"(off), "l"(src + k0 + cc * 4));
    }
    asm volatile("cp.async.commit_group;");
}

__global__ __launch_bounds__(640)
void router_kernel(const float* __restrict__ x, const float* __restrict__ Wg,
                   const float* __restrict__ bg, const float* __restrict__ A)
{
    __shared__ float sm[3 * RT_STG];
    __shared__ float ps[32 * 20];
    const uint32_t sb = smem_u32(sm);
    const int tid = threadIdx.x;
    const int t0 = blockIdx.x * 32;
    const int tok = tid / 20, j = tid % 20;

    float acc = 0.f;
    const int nChunk = DDIM / 32;

    rt_issue(sb, x, Wg, A, t0, 0, tid);
    rt_issue(sb + RT_STG * 4, x, Wg, A, t0, 32, tid);

    for (int c = 0; c < nChunk; c++) {
        if (c + 2 < nChunk) {
            asm volatile("cp.async.wait_group 1;");
        } else {
            asm volatile("cp.async.wait_group 0;");
        }
        __syncthreads();

        if (c + 2 < nChunk) {
            int wbuf = c + 2; while (wbuf >= 3) wbuf -= 3;
            rt_issue(sb + (uint32_t)(wbuf * RT_STG) * 4, x, Wg, A, t0, (c + 2) * 32, tid);
        }

        int buf = c; while (buf >= 3) buf -= 3;
        const float* xs = sm + buf * RT_STG;
        const float* ws = xs + RT_XW;

#pragma unroll
        for (int k4 = 0; k4 < 8; k4++) {
            float4 xv = *(const float4*)&xs[tok * 36 + k4 * 4];
            float4 wv = *(const float4*)&ws[j * 36 + k4 * 4];
            acc += xv.x * wv.x + xv.y * wv.y + xv.z * wv.z + xv.w * wv.w;
        }

        if (tid < 512) {
            int tk = tid >> 4, h = tid & 15;
            float lo = xs[tk * 36 + h * 2];
            float hi = xs[tk * 36 + h * 2 + 1];
            g_xh[(size_t)(t0 + tk) * (DDIM / 2) + c * 16 + h] = pack_h2(lo, hi);
        }
    }

    ps[tid] = acc;
    __syncthreads();

    if (tid < 32) {
        int t = t0 + tid;
        float l[4];
#pragma unroll
        for (int e = 0; e < 4; e++) l[e] = ps[tid * 20 + e] + bg[e];
        float m = fmaxf(fmaxf(l[0], l[1]), fmaxf(l[2], l[3]));
        float p[4], s = 0.f;
#pragma unroll
        for (int e = 0; e < 4; e++) { p[e] = expf(l[e] - m); s += p[e]; }
        float inv = 1.f / s;
#pragma unroll
        for (int e = 0; e < 4; e++) p[e] *= inv;
        int i1 = 0; float b1 = p[0];
#pragma unroll
        for (int e = 1; e < 4; e++) if (p[e] > b1) { b1 = p[e]; i1 = e; }
        int i2 = -1; float b2 = -1.f;
#pragma unroll
        for (int e = 0; e < 4; e++) if (e != i1 && p[e] > b2) { b2 = p[e]; i2 = e; }
        g_top[t] = make_float4(b1, b2, __int_as_float(i1), __int_as_float(i2));
#pragma unroll
        for (int i = 0; i < 16; i++)
            g_low[t * 16 + i] = ps[tid * 20 + 4 + i];
    }
}

// ---------------------------------------------------------------------------
// FP16 mma.sync m16n8k16 TN GEMM, 3-stage cp.async pipeline, ldmatrix loads.
// MODE 0: A=g_xh, B=g_wih, top-2 MoE epilogue -> g_hcomb; epilogue operands
//         (top/low/Bm) are cp.async-prefetched into the dead stage buffer
//         (buf 1, since nIter=16 -> 16%3==1) during the last mainloop iters.
// MODE 1: A=g_hcomb, B=g_woh -> Cout (fp32).
// ---------------------------------------------------------------------------
__device__ __forceinline__ void issue_tile(uint32_t sbaseA, const uint32_t* __restrict__ Ag,
                                           uint32_t sbaseB, const uint32_t* __restrict__ Bg,
                                           int Kw, int k0w, int tid)
{
#pragma unroll
    for (int t = 0; t < 4; t++) {           // 1024 chunks: 128 rows x 8 chunks
        int idx = tid + t * 256;
        int row = idx >> 3, c4 = idx & 7;
        uint32_t off = (uint32_t)(row * LDS_PAD + c4 * 4) * 4;
        const void* ga = Ag + (size_t)row * Kw + k0w + c4 * 4;
        const void* gb = Bg + (size_t)row * Kw + k0w + c4 * 4;
        asm volatile("cp.async.cg.shared.global [%0], [%1], 16;" :: "r"(sbaseA + off), "l"(ga));
        asm volatile("cp.async.cg.shared.global [%0], [%1], 16;" :: "r"(sbaseB + off), "l"(gb));
    }
}

// Epilogue prefetch into dead stage buffer: top 2KB @0, low 8KB @2048, bm 8KB @10240
__device__ __forceinline__ void issue_epi(uint32_t ebase, int m0, int n0,
                                          const float* __restrict__ pBm, int tid)
{
    if (tid < 128) {            // top: 128 x 16B
        const void* g = &g_top[m0 + tid];
        asm volatile("cp.async.cg.shared.global [%0], [%1], 16;"
                     :: "r"(ebase + (uint32_t)tid * 16), "l"(g));
    }
#pragma unroll
    for (int t = 0; t < 2; t++) {   // low: 512 x 16B
        int i = tid + t * 256;
        const void* g = &g_low[(size_t)(m0 + (i >> 2)) * 16 + (i & 3) * 4];
        asm volatile("cp.async.cg.shared.global [%0], [%1], 16;"
                     :: "r"(ebase + 2048u + (uint32_t)i * 16), "l"(g));
    }
#pragma unroll
    for (int t = 0; t < 2; t++) {   // bm: 512 x 16B  (layout [e][128 f][4 r])
        int i = tid + t * 256;
        int e = i >> 7, f = i & 127;
        const void* g = pBm + (size_t)e * (FDIM * 4) + (size_t)(n0 + f) * 4;
        asm volatile("cp.async.cg.shared.global [%0], [%1], 16;"
                     :: "r"(ebase + 10240u + (uint32_t)i * 16), "l"(g));
    }
    asm volatile("cp.async.commit_group;");
}

template <int MODE>
__global__ __launch_bounds__(256, 2)
void gemm_h(const uint32_t* __restrict__ Ain, const uint32_t* __restrict__ Bin,
            float* __restrict__ Cout, int Kw, const float* __restrict__ pBm)
{
    extern __shared__ uint32_t smem[];
    const uint32_t sb = smem_u32(smem);
    const int tid = threadIdx.x;
    const int wid = tid >> 5, lane = tid & 31;
    const int g = lane >> 2, q = lane & 3;
    const int wm = wid & 3, wn = wid >> 2;
    const int m0 = blockIdx.y * BM;
    const int n0 = blockIdx.x * BN;

    const uint32_t* Aptr = Ain + (size_t)m0 * Kw;
    const uint32_t* Bptr = Bin + (size_t)n0 * Kw;

    uint32_t a_base[2];
#pragma unroll
    for (int mt = 0; mt < 2; mt++) {
        int row = wm * 32 + mt * 16 + (lane & 15);
        a_base[mt] = (uint32_t)(row * (LDS_PAD * 4)) + ((lane >> 4) * 16);
    }
    uint32_t b_base[4];
#pragma unroll
    for (int ntp = 0; ntp < 4; ntp++) {
        int nrow = wn * 64 + ntp * 16 + (lane & 7) + ((lane & 16) ? 8 : 0);
        b_base[ntp] = (uint32_t)(TILE_WORDS * 4) + (uint32_t)(nrow * (LDS_PAD * 4))
                    + (((lane >> 3) & 1) * 16);
    }

    float acc[2][8][4];
#pragma unroll
    for (int mt = 0; mt < 2; mt++)
#pragma unroll
        for (int nt = 0; nt < 8; nt++)
#pragma unroll
            for (int e = 0; e < 4; e++) acc[mt][nt][e] = 0.f;

    const int nIter = Kw / BKW;                 // MODE0: 16, MODE1: 64
    const uint32_t ebase = sb + (uint32_t)STAGE_WORDS * 4;   // stage buffer 1

    issue_tile(sb, Aptr, sb + TILE_WORDS * 4, Bptr, Kw, 0, tid);
    asm volatile("cp.async.commit_group;");
    issue_tile(sb + STAGE_WORDS * 4, Aptr, sb + (STAGE_WORDS + TILE_WORDS) * 4, Bptr, Kw, BKW, tid);
    asm volatile("cp.async.commit_group;");

    int buf = 0;
    for (int i = 0; i < nIter; i++) {
        if (i + 1 < nIter) {
            asm volatile("cp.async.wait_group 1;");
        } else {
            asm volatile("cp.async.wait_group 0;");
        }
        __syncthreads();

        if (i + 2 < nIter) {
            int wbuf = buf + 2; if (wbuf >= NSTAGE) wbuf -= NSTAGE;
            uint32_t wb = sb + (uint32_t)(wbuf * STAGE_WORDS) * 4;
            issue_tile(wb, Aptr, wb + TILE_WORDS * 4, Bptr, Kw, (i + 2) * BKW, tid);
            asm volatile("cp.async.commit_group;");
        } else if (MODE == 0 && i + 2 == nIter) {
            // nIter=16: buffer (nIter % 3)=1 is dead; prefetch epilogue operands.
            issue_epi(ebase, m0, n0, pBm, tid);
        }

        const uint32_t sbuf = sb + (uint32_t)(buf * STAGE_WORDS) * 4;
#pragma unroll
        for (int kk = 0; kk < 4; kk++) {
            const uint32_t koff = (uint32_t)(kk * 32);
            uint32_t a[2][4];
            ldm_x4(a[0], sbuf + a_base[0] + koff);
            ldm_x4(a[1], sbuf + a_base[1] + koff);
#pragma unroll
            for (int ntp = 0; ntp < 4; ntp++) {
                uint32_t b[4];
                ldm_x4(b, sbuf + b_base[ntp] + koff);
#pragma unroll
                for (int mt = 0; mt < 2; mt++) {
                    mma_f16(acc[mt][2 * ntp],     a[mt], b);
                    mma_f16(acc[mt][2 * ntp + 1], a[mt], b + 2);
                }
            }
        }
        if (++buf >= NSTAGE) buf = 0;
    }

    if (MODE == 0) {
        // Top-2 MoE epilogue from prefetched smem (stage buffer 1):
        // h = w1*relu(base + low_{i1}.bm_{i1}) + w2*relu(base + low_{i2}.bm_{i2})
        const float4* top_s = (const float4*)(smem + STAGE_WORDS);
        const float*  low_s = (const float*)(smem + STAGE_WORDS + 512);
        const float*  bm_s  = (const float*)(smem + STAGE_WORDS + 2560);

#pragma unroll
        for (int mt = 0; mt < 2; mt++) {
#pragma unroll
            for (int half = 0; half < 2; half++) {
                int r = wm * 32 + mt * 16 + g + half * 8;     // local row
                float4 tv = top_s[r];
                float w1 = tv.x, w2 = tv.y;
                int i1 = __float_as_int(tv.z), i2 = __float_as_int(tv.w);
                float4 lv1 = *(const float4*)&low_s[r * 16 + i1 * 4];
                float4 lv2 = *(const float4*)&low_s[r * 16 + i2 * 4];
                uint32_t* dst = g_hcomb + (size_t)(m0 + r) * (FDIM / 2) + n0 / 2;
#pragma unroll
                for (int nt = 0; nt < 8; nt++) {
                    int cl = wn * 64 + nt * 8 + 2 * q;        // even column
                    float o[2];
#pragma unroll
                    for (int j = 0; j < 2; j++) {
                        float base = acc[mt][nt][half * 2 + j];
                        int col = cl + j;
                        float4 bm1 = *(const float4*)&bm_s[(i1 * 128 + col) * 4];
                        float4 bm2 = *(const float4*)&bm_s[(i2 * 128 + col) * 4];
                        float lo1 = lv1.x * bm1.x + lv1.y * bm1.y + lv1.z * bm1.z + lv1.w * bm1.w;
                        float lo2 = lv2.x * bm2.x + lv2.y * bm2.y + lv2.z * bm2.z + lv2.w * bm2.w;
                        o[j] = fmaf(w1, fmaxf(base + lo1, 0.f),
                                    w2 * fmaxf(base + lo2, 0.f));
                    }
                    dst[cl >> 1] = pack_h2(o[0], o[1]);
                }
            }
        }
    } else {
#pragma unroll
        for (int mt = 0; mt < 2; mt++) {
#pragma unroll
            for (int half = 0; half < 2; half++) {
                int r = wm * 32 + mt * 16 + g + half * 8;
                float* dst = Cout + (size_t)(m0 + r) * DDIM + n0;
#pragma unroll
                for (int nt = 0; nt < 8; nt++) {
                    int cl = wn * 64 + nt * 8 + 2 * q;
                    *(float2*)(dst + cl) =
                        make_float2(acc[mt][nt][half * 2], acc[mt][nt][half * 2 + 1]);
                }
            }
        }
    }
}

// ---------------------------------------------------------------------------
extern "C" void kernel_launch(void* const* d_in, const int* in_sizes, int n_in,
                              void* d_out, int out_size)
{
    const float* x  = (const float*)d_in[0];
    const float* Wg = (const float*)d_in[1];
    const float* bg = (const float*)d_in[2];
    const float* Wi = (const float*)d_in[3];
    const float* Wo = (const float*)d_in[4];
    const float* A  = (const float*)d_in[5];
    const float* Bm = (const float*)d_in[6];
    float* out = (float*)d_out;

    cudaFuncSetAttribute(gemm_h<0>, cudaFuncAttributeMaxDynamicSharedMemorySize, SMEM_BYTES_G);
    cudaFuncSetAttribute(gemm_h<1>, cudaFuncAttributeMaxDynamicSharedMemorySize, SMEM_BYTES_G);

    uint32_t* xh = nullptr;  cudaGetSymbolAddress((void**)&xh,  g_xh);
    uint32_t* wih = nullptr; cudaGetSymbolAddress((void**)&wih, g_wih);
    uint32_t* woh = nullptr; cudaGetSymbolAddress((void**)&woh, g_woh);
    uint32_t* hc = nullptr;  cudaGetSymbolAddress((void**)&hc,  g_hcomb);

    conv_h<<<1024, 256>>>((const float4*)Wi, (uint2*)wih, FDIM * DDIM / 4);
    conv_h<<<1024, 256>>>((const float4*)Wo, (uint2*)woh, DDIM * FDIM / 4);

    router_kernel<<<T_TOK / 32, 640>>>(x, Wg, bg, A);   // also writes g_xh

    gemm_h<0><<<dim3(FDIM / BN, T_TOK / BM), 256, SMEM_BYTES_G>>>(xh, wih, nullptr, DDIM / 2, Bm);
    gemm_h<1><<<dim3(DDIM / BN, T_TOK / BM), 256, SMEM_BYTES_G>>>(hc, woh, out, FDIM / 2, nullptr);
}